// round 11
// baseline (speedup 1.0000x reference)
#include <cuda_runtime.h>
#include <cstdint>

#define NN 50000
#define EE 800000
#define NBS 49   // ceil(NN/1024)

typedef unsigned long long u64;

// ---------------- scratch (device globals; no allocation allowed) ----------------
__device__ __align__(16) float g_h0[(size_t)NN * 128];   // layer input features
__device__ __align__(16) float g_h1[(size_t)NN * 128];   // h = x@W (interleaved [N][32][4])
__device__ __align__(16) float g_asrc[NN * 4];
__device__ __align__(16) float g_adst[NN * 4];
__device__ int g_deg[NN];
__device__ int g_ptr[NN + 1];
__device__ int g_bsum[64];
__device__ int g_csr[EE + NN];
__device__ int g_is64;

// ---------------- f32x2 helpers (scalar gemm32) ----------------
__device__ __forceinline__ u64 pack2(float x) {
    u64 r;
    asm("mov.b64 %0, {%1, %1};" : "=l"(r) : "f"(x));
    return r;
}
__device__ __forceinline__ void ffma2(u64& d, u64 a, u64 b) {
    asm("fma.rn.f32x2 %0, %1, %2, %0;" : "+l"(d) : "l"(a), "l"(b));
}
__device__ __forceinline__ void unpack2(u64 v, float& lo, float& hi) {
    asm("mov.b64 {%0, %1}, %2;" : "=f"(lo), "=f"(hi) : "l"(v));
}

// ---------------- tf32 helpers ----------------
__device__ __forceinline__ uint32_t f2tf(float x) {
    uint32_t u;
    asm("cvt.rna.tf32.f32 %0, %1;" : "=r"(u) : "f"(x));
    return u;
}
__device__ __forceinline__ void mma_tf32(float* c, const uint32_t* a, uint32_t b0, uint32_t b1) {
    asm volatile(
        "mma.sync.aligned.m16n8k8.row.col.f32.tf32.tf32.f32 "
        "{%0,%1,%2,%3}, {%4,%5,%6,%7}, {%8,%9}, {%0,%1,%2,%3};"
        : "+f"(c[0]), "+f"(c[1]), "+f"(c[2]), "+f"(c[3])
        : "r"(a[0]), "r"(a[1]), "r"(a[2]), "r"(a[3]), "r"(b0), "r"(b1));
}

// ---------------- CSR build ----------------
__global__ void detect_kernel(const int* __restrict__ e32) {
    __shared__ int any;
    if (threadIdx.x == 0) any = 0;
    __syncthreads();
    int local = 0;
    for (int i = threadIdx.x; i < 4096; i += blockDim.x)
        if (e32[2 * i + 1] != 0) local = 1;
    if (local) any = 1;
    __syncthreads();
    if (threadIdx.x == 0) g_is64 = (any == 0) ? 1 : 0;
}

__global__ void init_deg_kernel() {
    int n = blockIdx.x * blockDim.x + threadIdx.x;
    if (n < NN) g_deg[n] = 1;   // self loop
}

__global__ void hist_kernel(const void* __restrict__ ei) {
    int e = blockIdx.x * blockDim.x + threadIdx.x;
    if (e >= EE) return;
    int d = g_is64 ? (int)((const long long*)ei)[EE + e]
                   : ((const int*)ei)[EE + e];
    atomicAdd(&g_deg[d], 1);
}

__global__ void scan_local_kernel() {
    __shared__ int wsum[32];
    int t = threadIdx.x;
    int i = blockIdx.x * 1024 + t;
    int v = (i < NN) ? g_deg[i] : 0;
    int x = v;
    #pragma unroll
    for (int off = 1; off < 32; off <<= 1) {
        int y = __shfl_up_sync(0xffffffffu, x, off);
        if ((t & 31) >= off) x += y;
    }
    if ((t & 31) == 31) wsum[t >> 5] = x;
    __syncthreads();
    if (t < 32) {
        int w = wsum[t];
        #pragma unroll
        for (int off = 1; off < 32; off <<= 1) {
            int y = __shfl_up_sync(0xffffffffu, w, off);
            if (t >= off) w += y;
        }
        wsum[t] = w;
    }
    __syncthreads();
    int incl = x + ((t >= 32) ? wsum[(t >> 5) - 1] : 0);
    if (i < NN) g_ptr[i] = incl - v;
    if (t == 1023) g_bsum[blockIdx.x] = incl;
}

__global__ void scan_block_kernel() {   // 1 warp
    int t = threadIdx.x;
    int carry = 0;
    for (int base = 0; base < NBS; base += 32) {
        int v = (base + t < NBS) ? g_bsum[base + t] : 0;
        int x = v;
        #pragma unroll
        for (int off = 1; off < 32; off <<= 1) {
            int y = __shfl_up_sync(0xffffffffu, x, off);
            if (t >= off) x += y;
        }
        if (base + t < NBS) g_bsum[base + t] = carry + x - v;
        carry += __shfl_sync(0xffffffffu, x, 31);
    }
    if (t == 0) g_ptr[NN] = carry;
}

// finalize ptr AND place self-loop + reset cursor
__global__ void scan_add_kernel() {
    int i = blockIdx.x * 1024 + threadIdx.x;
    if (i < NN) {
        int p = g_ptr[i] + g_bsum[blockIdx.x];
        g_ptr[i] = p;
        g_csr[p] = i;    // self loop at slot 0
        g_deg[i] = 1;    // scatter cursor
    }
}

__global__ void scatter_kernel(const void* __restrict__ ei) {
    int e = blockIdx.x * blockDim.x + threadIdx.x;
    if (e >= EE) return;
    int s, d;
    if (g_is64) {
        s = (int)((const long long*)ei)[e];
        d = (int)((const long long*)ei)[EE + e];
    } else {
        s = ((const int*)ei)[e];
        d = ((const int*)ei)[EE + e];
    }
    int pos = atomicAdd(&g_deg[d], 1);
    g_csr[g_ptr[d] + pos] = s;
}

// ---------------- big GEMM via mma.sync tf32 (3xTF32), quad-interleaved fragments ----------------
// Block tile 128x128, K=128 in FOUR 32-wide chunks. 2 blocks/SM.
// Fragment quads: A quad at (row, ks, tig) = {hi(k0), hi(k1), lo(k0), lo(k1)}, k0=ks*8+tig, k1=k0+4
//                 B quad at (ks, tig, col) = same for W[k][col].
// One LDS.128 per fragment pair -> 8 LDS + 24 MMA per ks-step (was 32 LDS.32).
#define AQP 20    // A quad pitch per row (uint4s): 16 used + 4 pad (20 mod 8 = 4 -> conflict-free)
#define BQP 130   // B quad pitch per (ks,tig) row (uint4s): 128 used + 2 pad (130 mod 8 = 2)
#define SP 132    // stage pitch (floats)

__global__ __launch_bounds__(512, 2)
void gemm_tc_kernel(const float* __restrict__ X, const float* __restrict__ W,
                    const float* __restrict__ att_s, const float* __restrict__ att_d,
                    float* __restrict__ H, float* __restrict__ asrc,
                    float* __restrict__ adst) {
    extern __shared__ char sh[];
    float* att_ss = (float*)sh;                        // 128 f
    float* att_ds = (float*)(sh + 512);                // 128 f
    uint4* xs_q = (uint4*)(sh + 1024);                 // [128][AQP]
    uint4* ws_q = xs_q + 128 * AQP;                    // [16][BQP]
    float* stage = (float*)(sh + 1024);                // reused after mma

    int t = threadIdx.x;
    int lane = t & 31, wid = t >> 5;
    int g = lane >> 2, tig = lane & 3;
    int wm = wid >> 2, wn = wid & 3;
    int n0 = blockIdx.x * 128;

    if (t < 128) { att_ss[t] = att_s[t]; att_ds[t] = att_d[t]; }

    float acc[2][4][4];   // [mt 16-row][nt 8-col][frag]
    #pragma unroll
    for (int mt = 0; mt < 2; ++mt)
        #pragma unroll
        for (int nt = 0; nt < 4; ++nt)
            #pragma unroll
            for (int i = 0; i < 4; ++i) acc[mt][nt][i] = 0.f;

    uint32_t* xs_f = (uint32_t*)xs_q;
    uint32_t* ws_f = (uint32_t*)ws_q;

    for (int kc = 0; kc < 4; ++kc) {
        // load X[:, kc*32 .. +32) -> A quads  (128 rows x 8 float4)
        #pragma unroll 2
        for (int idx = t; idx < 128 * 8; idx += 512) {
            int r = idx >> 3, c4 = idx & 7;
            int n = n0 + r;
            float4 v = make_float4(0.f, 0.f, 0.f, 0.f);
            if (n < NN) v = ((const float4*)X)[(size_t)n * 32 + kc * 8 + c4];
            float e[4] = {v.x, v.y, v.z, v.w};
            #pragma unroll
            for (int j = 0; j < 4; ++j) {
                int kl = c4 * 4 + j;
                int ks = kl >> 3, tg = kl & 3, half = (kl >> 2) & 1;
                int qb = (r * AQP + ks * 4 + tg) * 4;
                uint32_t hu = f2tf(e[j]);
                float lo = e[j] - __uint_as_float(hu);
                xs_f[qb + half] = hu;
                xs_f[qb + 2 + half] = f2tf(lo);
            }
        }
        // load W[kc*32 .. +32, :] -> B quads  (32 k-rows x 32 float4)
        #pragma unroll 2
        for (int idx = t; idx < 32 * 32; idx += 512) {
            int kr = idx >> 5, c4 = idx & 31;
            float4 v = ((const float4*)W)[(size_t)(kc * 32 + kr) * 32 + c4];
            float e[4] = {v.x, v.y, v.z, v.w};
            int ks = kr >> 3, tg = kr & 3, half = (kr >> 2) & 1;
            int rowb = (ks * 4 + tg) * BQP;
            #pragma unroll
            for (int j = 0; j < 4; ++j) {
                int qb = (rowb + c4 * 4 + j) * 4;
                uint32_t hu = f2tf(e[j]);
                float lo = e[j] - __uint_as_float(hu);
                ws_f[qb + half] = hu;
                ws_f[qb + 2 + half] = f2tf(lo);
            }
        }
        __syncthreads();

        const uint4* xa = xs_q + (wm * 32 + g) * AQP + tig;
        const uint4* wb = ws_q + tig * BQP + wn * 32 + g;

        #pragma unroll
        for (int ks = 0; ks < 4; ++ks) {
            uint32_t ah[2][4], al[2][4];
            #pragma unroll
            for (int mt = 0; mt < 2; ++mt) {
                uint4 q0 = xa[mt * 16 * AQP + ks * 4];              // row g
                uint4 q1 = xa[(mt * 16 + 8) * AQP + ks * 4];        // row g+8
                ah[mt][0] = q0.x; ah[mt][1] = q1.x; ah[mt][2] = q0.y; ah[mt][3] = q1.y;
                al[mt][0] = q0.z; al[mt][1] = q1.z; al[mt][2] = q0.w; al[mt][3] = q1.w;
            }
            #pragma unroll
            for (int nt = 0; nt < 4; ++nt) {
                uint4 qb = wb[ks * 4 * BQP + nt * 8];
                #pragma unroll
                for (int mt = 0; mt < 2; ++mt) {
                    mma_tf32(acc[mt][nt], ah[mt], qb.x, qb.y);   // hi*hi
                    mma_tf32(acc[mt][nt], al[mt], qb.x, qb.y);   // lo*hi
                    mma_tf32(acc[mt][nt], ah[mt], qb.z, qb.w);   // hi*lo
                }
            }
        }
        __syncthreads();
    }

    // ---- epilogue: attention dots (warp covers exactly head wn) ----
    #pragma unroll
    for (int mt = 0; mt < 2; ++mt) {
        #pragma unroll
        for (int rh = 0; rh < 2; ++rh) {
            int n = n0 + wm * 32 + mt * 16 + g + rh * 8;
            float ps = 0.f, pd = 0.f;
            #pragma unroll
            for (int nt = 0; nt < 4; ++nt) {
                #pragma unroll
                for (int ci = 0; ci < 2; ++ci) {
                    int col = wn * 32 + nt * 8 + 2 * tig + ci;
                    float a = acc[mt][nt][rh * 2 + ci];
                    ps += a * att_ss[col];
                    pd += a * att_ds[col];
                }
            }
            #pragma unroll
            for (int off = 1; off <= 2; off <<= 1) {
                ps += __shfl_xor_sync(0xffffffffu, ps, off);
                pd += __shfl_xor_sync(0xffffffffu, pd, off);
            }
            if (tig == 0 && n < NN) {
                asrc[n * 4 + wn] = ps;
                adst[n * 4 + wn] = pd;
            }
        }
    }

    // ---- stage accs to smem, then interleaved H store ----
    #pragma unroll
    for (int mt = 0; mt < 2; ++mt) {
        int rbase = wm * 32 + mt * 16 + g;
        #pragma unroll
        for (int nt = 0; nt < 4; ++nt) {
            int col = wn * 32 + nt * 8 + 2 * tig;
            stage[rbase * SP + col] = acc[mt][nt][0];
            stage[rbase * SP + col + 1] = acc[mt][nt][1];
            stage[(rbase + 8) * SP + col] = acc[mt][nt][2];
            stage[(rbase + 8) * SP + col + 1] = acc[mt][nt][3];
        }
    }
    __syncthreads();
    #pragma unroll 2
    for (int idx = t; idx < 128 * 32; idx += 512) {
        int r = idx >> 5, fc = idx & 31;
        int n = n0 + r;
        if (n < NN) {
            const float* sr = stage + r * SP;
            ((float4*)H)[(size_t)n * 32 + fc] =
                make_float4(sr[fc], sr[32 + fc], sr[64 + fc], sr[96 + fc]);
        }
    }
}

// ---------------- small GEMM (M=32, heads=1, scalar f32x2) ----------------
__launch_bounds__(256)
__global__ void gemm32_kernel(const float* __restrict__ X, const float* __restrict__ W,
                              const float* __restrict__ att_s, const float* __restrict__ att_d,
                              float* __restrict__ H, float* __restrict__ asrc,
                              float* __restrict__ adst) {
    constexpr int CG = 8;
    constexpr int RPT = 2;
    constexpr int XS = 132;
    extern __shared__ float shf[];
    float* ws = shf;                 // 128*32
    float* xs = shf + 128 * 32;      // 64*XS

    int t = threadIdx.x;
    int n0 = blockIdx.x * 64;

    for (int i = t; i < 128 * 32 / 4; i += 256)
        ((float4*)ws)[i] = ((const float4*)W)[i];
    for (int i = t; i < 64 * 32; i += 256) {
        int r = i >> 5, c = i & 31;
        int n = n0 + r;
        float4 v = make_float4(0.f, 0.f, 0.f, 0.f);
        if (n < NN) v = ((const float4*)X)[(size_t)n * 32 + c];
        *((float4*)(xs + r * XS + c * 4)) = v;
    }
    __syncthreads();

    int cg = t % CG;
    int rg = t / CG;

    u64 acc2[RPT][2];
    #pragma unroll
    for (int r = 0; r < RPT; ++r) { acc2[r][0] = 0ull; acc2[r][1] = 0ull; }

    const ulonglong2* wsp = (const ulonglong2*)ws;
    #pragma unroll 8
    for (int k = 0; k < 128; ++k) {
        ulonglong2 wp = wsp[k * CG + cg];
        #pragma unroll
        for (int r = 0; r < RPT; ++r) {
            u64 xp = pack2(xs[(rg * RPT + r) * XS + k]);
            ffma2(acc2[r][0], xp, wp.x);
            ffma2(acc2[r][1], xp, wp.y);
        }
    }

    float4 as = ((const float4*)att_s)[cg];
    float4 ad = ((const float4*)att_d)[cg];
    #pragma unroll
    for (int r = 0; r < RPT; ++r) {
        float acc[4];
        unpack2(acc2[r][0], acc[0], acc[1]);
        unpack2(acc2[r][1], acc[2], acc[3]);
        int n = n0 + rg * RPT + r;
        float ps = acc[0] * as.x + acc[1] * as.y + acc[2] * as.z + acc[3] * as.w;
        float pd = acc[0] * ad.x + acc[1] * ad.y + acc[2] * ad.z + acc[3] * ad.w;
        #pragma unroll
        for (int off = 4; off >= 1; off >>= 1) {
            ps += __shfl_down_sync(0xffffffffu, ps, off, 8);
            pd += __shfl_down_sync(0xffffffffu, pd, off, 8);
        }
        if ((t & 7) == 0 && n < NN) {
            asrc[n] = ps;
            adst[n] = pd;
        }
        if (n < NN)
            ((float4*)H)[(size_t)n * CG + cg] = make_float4(acc[0], acc[1], acc[2], acc[3]);
    }
}

// ---------------- per-node ONLINE softmax + aggregation (single edge pass) ----------------
__device__ __forceinline__ float lrelu(float v) { return fmaxf(v, 0.2f * v); }

template <int HEADS, int ACT>   // ACT: 0 = ELU, 1 = sigmoid
__launch_bounds__(256)
__global__ void agg_kernel(const float* __restrict__ feat,
                           const float* __restrict__ asrc, const float* __restrict__ adst,
                           const float* __restrict__ bias, float* __restrict__ out) {
    __shared__ float4 s_w4[8][32];
    __shared__ int s_src[8][32];
    int wid = threadIdx.x >> 5;
    int lane = threadIdx.x & 31;
    int n = blockIdx.x * 8 + wid;
    if (n >= NN) return;
    int beg = g_ptr[n], end = g_ptr[n + 1];
    const float4* feat4 = (const float4*)feat;

    if (HEADS == 4) {
        float4 ad = ((const float4*)adst)[n];
        float m0 = -1e30f, m1 = -1e30f, m2 = -1e30f, m3 = -1e30f;
        float a0 = 0.f, a1 = 0.f, a2 = 0.f, a3 = 0.f;
        float s0 = 0.f, s1 = 0.f, s2 = 0.f, s3 = 0.f;
        for (int base = beg; base < end; base += 32) {
            int cnt = min(32, end - base);
            float l0 = -1e30f, l1 = -1e30f, l2 = -1e30f, l3 = -1e30f;
            int src = 0;
            if (lane < cnt) {
                src = g_csr[base + lane];
                float4 a = ((const float4*)asrc)[src];
                l0 = lrelu(a.x + ad.x);
                l1 = lrelu(a.y + ad.y);
                l2 = lrelu(a.z + ad.z);
                l3 = lrelu(a.w + ad.w);
            }
            float c0 = l0, c1 = l1, c2 = l2, c3 = l3;
            #pragma unroll
            for (int off = 16; off >= 1; off >>= 1) {
                c0 = fmaxf(c0, __shfl_xor_sync(0xffffffffu, c0, off));
                c1 = fmaxf(c1, __shfl_xor_sync(0xffffffffu, c1, off));
                c2 = fmaxf(c2, __shfl_xor_sync(0xffffffffu, c2, off));
                c3 = fmaxf(c3, __shfl_xor_sync(0xffffffffu, c3, off));
            }
            float nm0 = fmaxf(m0, c0), nm1 = fmaxf(m1, c1);
            float nm2 = fmaxf(m2, c2), nm3 = fmaxf(m3, c3);
            float f0 = __expf(m0 - nm0), f1 = __expf(m1 - nm1);
            float f2 = __expf(m2 - nm2), f3 = __expf(m3 - nm3);
            a0 *= f0; a1 *= f1; a2 *= f2; a3 *= f3;
            s0 *= f0; s1 *= f1; s2 *= f2; s3 *= f3;
            m0 = nm0; m1 = nm1; m2 = nm2; m3 = nm3;
            if (lane < cnt) {
                float4 wv;
                wv.x = __expf(l0 - m0);
                wv.y = __expf(l1 - m1);
                wv.z = __expf(l2 - m2);
                wv.w = __expf(l3 - m3);
                s_w4[wid][lane] = wv;
                s_src[wid][lane] = src;
            }
            __syncwarp();
            for (int i = 0; i < cnt; ++i) {
                float4 wv = s_w4[wid][i];
                int si = s_src[wid][i];
                float4 v = feat4[(size_t)si * 32 + lane];
                a0 += wv.x * v.x; a1 += wv.y * v.y; a2 += wv.z * v.z; a3 += wv.w * v.w;
                s0 += wv.x; s1 += wv.y; s2 += wv.z; s3 += wv.w;
            }
            __syncwarp();
        }
        float o0 = a0 / s0 + bias[lane];
        float o1 = a1 / s1 + bias[32 + lane];
        float o2 = a2 / s2 + bias[64 + lane];
        float o3 = a3 / s3 + bias[96 + lane];
        o0 = (o0 > 0.f) ? o0 : (__expf(o0) - 1.f);
        o1 = (o1 > 0.f) ? o1 : (__expf(o1) - 1.f);
        o2 = (o2 > 0.f) ? o2 : (__expf(o2) - 1.f);
        o3 = (o3 > 0.f) ? o3 : (__expf(o3) - 1.f);
        size_t b = (size_t)n * 128;
        out[b + lane] = o0;
        out[b + 32 + lane] = o1;
        out[b + 64 + lane] = o2;
        out[b + 96 + lane] = o3;
    } else {
        float* s_wf = (float*)&s_w4[wid][0];
        float ad = adst[n];
        float m = -1e30f, acc = 0.f, ssum = 0.f;
        for (int base = beg; base < end; base += 32) {
            int cnt = min(32, end - base);
            float l = -1e30f;
            int src = 0;
            if (lane < cnt) {
                src = g_csr[base + lane];
                l = lrelu(asrc[src] + ad);
            }
            float c = l;
            #pragma unroll
            for (int off = 16; off >= 1; off >>= 1)
                c = fmaxf(c, __shfl_xor_sync(0xffffffffu, c, off));
            float nm = fmaxf(m, c);
            float f = __expf(m - nm);
            acc *= f; ssum *= f;
            m = nm;
            if (lane < cnt) {
                s_wf[lane] = __expf(l - m);
                s_src[wid][lane] = src;
            }
            __syncwarp();
            for (int i = 0; i < cnt; ++i) {
                float wi = s_wf[i];
                int si = s_src[wid][i];
                acc += wi * feat[(size_t)si * 32 + lane];
                ssum += wi;
            }
            __syncwarp();
        }
        float o = acc / ssum + bias[lane];
        o = 1.f / (1.f + __expf(-o));
        out[(size_t)n * 32 + lane] = o;
    }
}

// ---------------- host launcher (single stream, capture-safe) ----------------
extern "C" void kernel_launch(void* const* d_in, const int* in_sizes, int n_in,
                              void* d_out, int out_size) {
    const float* x = (const float*)d_in[0];
    const void* ei = d_in[1];
    const float* W[4]  = {(const float*)d_in[2], (const float*)d_in[6],
                          (const float*)d_in[10], (const float*)d_in[14]};
    const float* As[4] = {(const float*)d_in[3], (const float*)d_in[7],
                          (const float*)d_in[11], (const float*)d_in[15]};
    const float* Ad[4] = {(const float*)d_in[4], (const float*)d_in[8],
                          (const float*)d_in[12], (const float*)d_in[16]};
    const float* B[4]  = {(const float*)d_in[5], (const float*)d_in[9],
                          (const float*)d_in[13], (const float*)d_in[17]};
    float* out = (float*)d_out;

    float *p_h0, *p_h1, *p_asrc, *p_adst;
    cudaGetSymbolAddress((void**)&p_h0, g_h0);
    cudaGetSymbolAddress((void**)&p_h1, g_h1);
    cudaGetSymbolAddress((void**)&p_asrc, g_asrc);
    cudaGetSymbolAddress((void**)&p_adst, g_adst);

    constexpr int SMEM_TC = 1024 + (128 * AQP + 16 * BQP) * 16;   // 1024+40960+33280 = 75264 B
    constexpr int SMEM_SMALL = (128 * 32 + 64 * 132) * 4;         // 50176 B
    cudaFuncSetAttribute(gemm_tc_kernel,
                         cudaFuncAttributeMaxDynamicSharedMemorySize, SMEM_TC);
    cudaFuncSetAttribute(gemm32_kernel,
                         cudaFuncAttributeMaxDynamicSharedMemorySize, SMEM_SMALL);

    const int GTC = (NN + 127) / 128;  // 391
    const int GB = (NN + 63) / 64;     // 782
    const int AB = (NN + 7) / 8;       // 6250

    // CSR build, with layer-1 GEMM (CSR-independent) slotted at launch index 3
    // so the ncu capture lands on it.
    detect_kernel<<<1, 256>>>((const int*)ei);                             // 0
    init_deg_kernel<<<(NN + 255) / 256, 256>>>();                          // 1
    hist_kernel<<<(EE + 255) / 256, 256>>>(ei);                            // 2
    gemm_tc_kernel<<<GTC, 512, SMEM_TC>>>(x, W[0], As[0], Ad[0],           // 3 (profiled)
                                          p_h1, p_asrc, p_adst);
    scan_local_kernel<<<NBS, 1024>>>();                                    // 4
    scan_block_kernel<<<1, 32>>>();                                        // 5
    scan_add_kernel<<<NBS, 1024>>>();                                      // 6
    scatter_kernel<<<(EE + 255) / 256, 256>>>(ei);                         // 7

    // layer 1 aggregation
    agg_kernel<4, 0><<<AB, 256>>>(p_h1, p_asrc, p_adst, B[0], p_h0);
    // layer 2
    gemm_tc_kernel<<<GTC, 512, SMEM_TC>>>(p_h0, W[1], As[1], Ad[1], p_h1, p_asrc, p_adst);
    agg_kernel<4, 0><<<AB, 256>>>(p_h1, p_asrc, p_adst, B[1], p_h0);
    // layer 3
    gemm_tc_kernel<<<GTC, 512, SMEM_TC>>>(p_h0, W[2], As[2], Ad[2], p_h1, p_asrc, p_adst);
    agg_kernel<4, 0><<<AB, 256>>>(p_h1, p_asrc, p_adst, B[2], p_h0);
    // layer 4 (heads=1, 32 labels) -> sigmoid -> d_out
    gemm32_kernel<<<GB, 256, SMEM_SMALL>>>(p_h0, W[3], As[3], Ad[3], p_h1, p_asrc, p_adst);
    agg_kernel<1, 1><<<AB, 256>>>(p_h1, p_asrc, p_adst, B[3], out);
}

// round 12
// speedup vs baseline: 1.1758x; 1.1758x over previous
#include <cuda_runtime.h>
#include <cstdint>

#define NN 50000
#define EE 800000
#define NBS 49   // ceil(NN/1024)

typedef unsigned long long u64;

// ---------------- scratch (device globals; no allocation allowed) ----------------
__device__ __align__(16) float g_h0[(size_t)NN * 128];   // layer input features
__device__ __align__(16) float g_h1[(size_t)NN * 128];   // h = x@W (interleaved [N][32][4])
__device__ __align__(16) float g_asrc[NN * 4];
__device__ __align__(16) float g_adst[NN * 4];
__device__ int g_deg[NN];
__device__ int g_ptr[NN + 1];
__device__ int g_bsum[64];
__device__ int g_csr[EE + NN];
__device__ int g_is64;

// ---------------- f32x2 helpers (scalar gemm32) ----------------
__device__ __forceinline__ u64 pack2(float x) {
    u64 r;
    asm("mov.b64 %0, {%1, %1};" : "=l"(r) : "f"(x));
    return r;
}
__device__ __forceinline__ void ffma2(u64& d, u64 a, u64 b) {
    asm("fma.rn.f32x2 %0, %1, %2, %0;" : "+l"(d) : "l"(a), "l"(b));
}
__device__ __forceinline__ void unpack2(u64 v, float& lo, float& hi) {
    asm("mov.b64 {%0, %1}, %2;" : "=f"(lo), "=f"(hi) : "l"(v));
}

// ---------------- tf32 helpers ----------------
__device__ __forceinline__ uint32_t f2tf(float x) {
    uint32_t u;
    asm("cvt.rna.tf32.f32 %0, %1;" : "=r"(u) : "f"(x));
    return u;
}
__device__ __forceinline__ void mma_tf32(float* c, const uint32_t* a, uint32_t b0, uint32_t b1) {
    asm volatile(
        "mma.sync.aligned.m16n8k8.row.col.f32.tf32.tf32.f32 "
        "{%0,%1,%2,%3}, {%4,%5,%6,%7}, {%8,%9}, {%0,%1,%2,%3};"
        : "+f"(c[0]), "+f"(c[1]), "+f"(c[2]), "+f"(c[3])
        : "r"(a[0]), "r"(a[1]), "r"(a[2]), "r"(a[3]), "r"(b0), "r"(b1));
}

// ---------------- CSR build ----------------
__global__ void detect_kernel(const int* __restrict__ e32) {
    __shared__ int any;
    if (threadIdx.x == 0) any = 0;
    __syncthreads();
    int local = 0;
    for (int i = threadIdx.x; i < 4096; i += blockDim.x)
        if (e32[2 * i + 1] != 0) local = 1;
    if (local) any = 1;
    __syncthreads();
    if (threadIdx.x == 0) g_is64 = (any == 0) ? 1 : 0;
}

__global__ void init_deg_kernel() {
    int n = blockIdx.x * blockDim.x + threadIdx.x;
    if (n < NN) g_deg[n] = 1;   // self loop
}

__global__ void hist_kernel(const void* __restrict__ ei) {
    int e = blockIdx.x * blockDim.x + threadIdx.x;
    if (e >= EE) return;
    int d = g_is64 ? (int)((const long long*)ei)[EE + e]
                   : ((const int*)ei)[EE + e];
    atomicAdd(&g_deg[d], 1);
}

__global__ void scan_local_kernel() {
    __shared__ int wsum[32];
    int t = threadIdx.x;
    int i = blockIdx.x * 1024 + t;
    int v = (i < NN) ? g_deg[i] : 0;
    int x = v;
    #pragma unroll
    for (int off = 1; off < 32; off <<= 1) {
        int y = __shfl_up_sync(0xffffffffu, x, off);
        if ((t & 31) >= off) x += y;
    }
    if ((t & 31) == 31) wsum[t >> 5] = x;
    __syncthreads();
    if (t < 32) {
        int w = wsum[t];
        #pragma unroll
        for (int off = 1; off < 32; off <<= 1) {
            int y = __shfl_up_sync(0xffffffffu, w, off);
            if (t >= off) w += y;
        }
        wsum[t] = w;
    }
    __syncthreads();
    int incl = x + ((t >= 32) ? wsum[(t >> 5) - 1] : 0);
    if (i < NN) g_ptr[i] = incl - v;
    if (t == 1023) g_bsum[blockIdx.x] = incl;
}

__global__ void scan_block_kernel() {   // 1 warp
    int t = threadIdx.x;
    int carry = 0;
    for (int base = 0; base < NBS; base += 32) {
        int v = (base + t < NBS) ? g_bsum[base + t] : 0;
        int x = v;
        #pragma unroll
        for (int off = 1; off < 32; off <<= 1) {
            int y = __shfl_up_sync(0xffffffffu, x, off);
            if (t >= off) x += y;
        }
        if (base + t < NBS) g_bsum[base + t] = carry + x - v;
        carry += __shfl_sync(0xffffffffu, x, 31);
    }
    if (t == 0) g_ptr[NN] = carry;
}

// finalize ptr AND place self-loop + reset cursor
__global__ void scan_add_kernel() {
    int i = blockIdx.x * 1024 + threadIdx.x;
    if (i < NN) {
        int p = g_ptr[i] + g_bsum[blockIdx.x];
        g_ptr[i] = p;
        g_csr[p] = i;    // self loop at slot 0
        g_deg[i] = 1;    // scatter cursor
    }
}

__global__ void scatter_kernel(const void* __restrict__ ei) {
    int e = blockIdx.x * blockDim.x + threadIdx.x;
    if (e >= EE) return;
    int s, d;
    if (g_is64) {
        s = (int)((const long long*)ei)[e];
        d = (int)((const long long*)ei)[EE + e];
    } else {
        s = ((const int*)ei)[e];
        d = ((const int*)ei)[EE + e];
    }
    int pos = atomicAdd(&g_deg[d], 1);
    g_csr[g_ptr[d] + pos] = s;
}

// ---------------- big GEMM via mma.sync tf32 (3xTF32) ----------------
// Block tile 128x128, K=128 in FOUR 32-wide chunks, 2 blocks/SM.
// A: separate hi/lo scalar arrays (round-9 proven, no quad register pressure).
// B: quad-interleaved {hi(k0),hi(k1),lo(k0),lo(k1)} -> one transient LDS.128 per nt.
#define XP2 36    // A pitch (floats) for 32-wide K chunk
#define BQP 130   // B quad pitch per (ks,tig) row (uint4s): 128 used + 2 pad
#define SP 132    // stage pitch (floats)

__global__ __launch_bounds__(512, 2)
void gemm_tc_kernel(const float* __restrict__ X, const float* __restrict__ W,
                    const float* __restrict__ att_s, const float* __restrict__ att_d,
                    float* __restrict__ H, float* __restrict__ asrc,
                    float* __restrict__ adst) {
    extern __shared__ char sh[];
    float* att_ss = (float*)sh;                        // 128 f
    float* att_ds = (float*)(sh + 512);                // 128 f
    uint32_t* xs_hi = (uint32_t*)(sh + 1024);          // [128][XP2]
    uint32_t* xs_lo = xs_hi + 128 * XP2;
    uint4* ws_q = (uint4*)(xs_lo + 128 * XP2);         // [16][BQP]
    float* stage = (float*)(sh + 1024);                // reused after mma

    int t = threadIdx.x;
    int lane = t & 31, wid = t >> 5;
    int g = lane >> 2, tig = lane & 3;
    int wm = wid >> 2, wn = wid & 3;
    int n0 = blockIdx.x * 128;

    if (t < 128) { att_ss[t] = att_s[t]; att_ds[t] = att_d[t]; }

    float acc[2][4][4];   // [mt 16-row][nt 8-col][frag]
    #pragma unroll
    for (int mt = 0; mt < 2; ++mt)
        #pragma unroll
        for (int nt = 0; nt < 4; ++nt)
            #pragma unroll
            for (int i = 0; i < 4; ++i) acc[mt][nt][i] = 0.f;

    uint32_t* ws_f = (uint32_t*)ws_q;

    for (int kc = 0; kc < 4; ++kc) {
        // load X[:, kc*32 .. +32) -> xs hi/lo  (128 rows x 8 float4)
        #pragma unroll 2
        for (int idx = t; idx < 128 * 8; idx += 512) {
            int r = idx >> 3, c4 = idx & 7;
            int n = n0 + r;
            float4 v = make_float4(0.f, 0.f, 0.f, 0.f);
            if (n < NN) v = ((const float4*)X)[(size_t)n * 32 + kc * 8 + c4];
            float e[4] = {v.x, v.y, v.z, v.w};
            #pragma unroll
            for (int j = 0; j < 4; ++j) {
                uint32_t hu = f2tf(e[j]);
                float lo = e[j] - __uint_as_float(hu);
                xs_hi[r * XP2 + c4 * 4 + j] = hu;
                xs_lo[r * XP2 + c4 * 4 + j] = f2tf(lo);
            }
        }
        // load W[kc*32 .. +32, :] -> B quads  (32 k-rows x 32 float4)
        #pragma unroll 2
        for (int idx = t; idx < 32 * 32; idx += 512) {
            int kr = idx >> 5, c4 = idx & 31;
            float4 v = ((const float4*)W)[(size_t)(kc * 32 + kr) * 32 + c4];
            float e[4] = {v.x, v.y, v.z, v.w};
            int ks = kr >> 3, tg = kr & 3, half = (kr >> 2) & 1;
            int rowb = (ks * 4 + tg) * BQP;
            #pragma unroll
            for (int j = 0; j < 4; ++j) {
                int qb = (rowb + c4 * 4 + j) * 4;
                uint32_t hu = f2tf(e[j]);
                float lo = e[j] - __uint_as_float(hu);
                ws_f[qb + half] = hu;
                ws_f[qb + 2 + half] = f2tf(lo);
            }
        }
        __syncthreads();

        const uint32_t* xa_h = xs_hi + (wm * 32 + g) * XP2 + tig;
        const uint32_t* xa_l = xs_lo + (wm * 32 + g) * XP2 + tig;
        const uint4* wb = ws_q + tig * BQP + wn * 32 + g;

        #pragma unroll
        for (int ks = 0; ks < 4; ++ks) {
            uint32_t ah[2][4], al[2][4];
            #pragma unroll
            for (int mt = 0; mt < 2; ++mt) {
                int base = mt * 16 * XP2 + ks * 8;
                ah[mt][0] = xa_h[base];
                ah[mt][1] = xa_h[base + 8 * XP2];
                ah[mt][2] = xa_h[base + 4];
                ah[mt][3] = xa_h[base + 8 * XP2 + 4];
                al[mt][0] = xa_l[base];
                al[mt][1] = xa_l[base + 8 * XP2];
                al[mt][2] = xa_l[base + 4];
                al[mt][3] = xa_l[base + 8 * XP2 + 4];
            }
            #pragma unroll
            for (int nt = 0; nt < 4; ++nt) {
                uint4 qb = wb[ks * 4 * BQP + nt * 8];
                #pragma unroll
                for (int mt = 0; mt < 2; ++mt) {
                    mma_tf32(acc[mt][nt], ah[mt], qb.x, qb.y);   // hi*hi
                    mma_tf32(acc[mt][nt], al[mt], qb.x, qb.y);   // lo*hi
                    mma_tf32(acc[mt][nt], ah[mt], qb.z, qb.w);   // hi*lo
                }
            }
        }
        __syncthreads();
    }

    // ---- epilogue: attention dots (warp covers exactly head wn) ----
    #pragma unroll
    for (int mt = 0; mt < 2; ++mt) {
        #pragma unroll
        for (int rh = 0; rh < 2; ++rh) {
            int n = n0 + wm * 32 + mt * 16 + g + rh * 8;
            float ps = 0.f, pd = 0.f;
            #pragma unroll
            for (int nt = 0; nt < 4; ++nt) {
                #pragma unroll
                for (int ci = 0; ci < 2; ++ci) {
                    int col = wn * 32 + nt * 8 + 2 * tig + ci;
                    float a = acc[mt][nt][rh * 2 + ci];
                    ps += a * att_ss[col];
                    pd += a * att_ds[col];
                }
            }
            #pragma unroll
            for (int off = 1; off <= 2; off <<= 1) {
                ps += __shfl_xor_sync(0xffffffffu, ps, off);
                pd += __shfl_xor_sync(0xffffffffu, pd, off);
            }
            if (tig == 0 && n < NN) {
                asrc[n * 4 + wn] = ps;
                adst[n * 4 + wn] = pd;
            }
        }
    }

    // ---- stage accs to smem, then interleaved H store ----
    #pragma unroll
    for (int mt = 0; mt < 2; ++mt) {
        int rbase = wm * 32 + mt * 16 + g;
        #pragma unroll
        for (int nt = 0; nt < 4; ++nt) {
            int col = wn * 32 + nt * 8 + 2 * tig;
            stage[rbase * SP + col] = acc[mt][nt][0];
            stage[rbase * SP + col + 1] = acc[mt][nt][1];
            stage[(rbase + 8) * SP + col] = acc[mt][nt][2];
            stage[(rbase + 8) * SP + col + 1] = acc[mt][nt][3];
        }
    }
    __syncthreads();
    #pragma unroll 2
    for (int idx = t; idx < 128 * 32; idx += 512) {
        int r = idx >> 5, fc = idx & 31;
        int n = n0 + r;
        if (n < NN) {
            const float* sr = stage + r * SP;
            ((float4*)H)[(size_t)n * 32 + fc] =
                make_float4(sr[fc], sr[32 + fc], sr[64 + fc], sr[96 + fc]);
        }
    }
}

// ---------------- small GEMM (M=32, heads=1, scalar f32x2) ----------------
__launch_bounds__(256)
__global__ void gemm32_kernel(const float* __restrict__ X, const float* __restrict__ W,
                              const float* __restrict__ att_s, const float* __restrict__ att_d,
                              float* __restrict__ H, float* __restrict__ asrc,
                              float* __restrict__ adst) {
    constexpr int CG = 8;
    constexpr int RPT = 2;
    constexpr int XS = 132;
    extern __shared__ float shf[];
    float* ws = shf;                 // 128*32
    float* xs = shf + 128 * 32;      // 64*XS

    int t = threadIdx.x;
    int n0 = blockIdx.x * 64;

    for (int i = t; i < 128 * 32 / 4; i += 256)
        ((float4*)ws)[i] = ((const float4*)W)[i];
    for (int i = t; i < 64 * 32; i += 256) {
        int r = i >> 5, c = i & 31;
        int n = n0 + r;
        float4 v = make_float4(0.f, 0.f, 0.f, 0.f);
        if (n < NN) v = ((const float4*)X)[(size_t)n * 32 + c];
        *((float4*)(xs + r * XS + c * 4)) = v;
    }
    __syncthreads();

    int cg = t % CG;
    int rg = t / CG;

    u64 acc2[RPT][2];
    #pragma unroll
    for (int r = 0; r < RPT; ++r) { acc2[r][0] = 0ull; acc2[r][1] = 0ull; }

    const ulonglong2* wsp = (const ulonglong2*)ws;
    #pragma unroll 8
    for (int k = 0; k < 128; ++k) {
        ulonglong2 wp = wsp[k * CG + cg];
        #pragma unroll
        for (int r = 0; r < RPT; ++r) {
            u64 xp = pack2(xs[(rg * RPT + r) * XS + k]);
            ffma2(acc2[r][0], xp, wp.x);
            ffma2(acc2[r][1], xp, wp.y);
        }
    }

    float4 as = ((const float4*)att_s)[cg];
    float4 ad = ((const float4*)att_d)[cg];
    #pragma unroll
    for (int r = 0; r < RPT; ++r) {
        float acc[4];
        unpack2(acc2[r][0], acc[0], acc[1]);
        unpack2(acc2[r][1], acc[2], acc[3]);
        int n = n0 + rg * RPT + r;
        float ps = acc[0] * as.x + acc[1] * as.y + acc[2] * as.z + acc[3] * as.w;
        float pd = acc[0] * ad.x + acc[1] * ad.y + acc[2] * ad.z + acc[3] * ad.w;
        #pragma unroll
        for (int off = 4; off >= 1; off >>= 1) {
            ps += __shfl_down_sync(0xffffffffu, ps, off, 8);
            pd += __shfl_down_sync(0xffffffffu, pd, off, 8);
        }
        if ((t & 7) == 0 && n < NN) {
            asrc[n] = ps;
            adst[n] = pd;
        }
        if (n < NN)
            ((float4*)H)[(size_t)n * CG + cg] = make_float4(acc[0], acc[1], acc[2], acc[3]);
    }
}

// ---------------- per-node ONLINE softmax + aggregation (single edge pass) ----------------
__device__ __forceinline__ float lrelu(float v) { return fmaxf(v, 0.2f * v); }

template <int HEADS, int ACT>   // ACT: 0 = ELU, 1 = sigmoid
__launch_bounds__(256)
__global__ void agg_kernel(const float* __restrict__ feat,
                           const float* __restrict__ asrc, const float* __restrict__ adst,
                           const float* __restrict__ bias, float* __restrict__ out) {
    __shared__ float4 s_w4[8][32];
    __shared__ int s_src[8][32];
    int wid = threadIdx.x >> 5;
    int lane = threadIdx.x & 31;
    int n = blockIdx.x * 8 + wid;
    if (n >= NN) return;
    int beg = g_ptr[n], end = g_ptr[n + 1];
    const float4* feat4 = (const float4*)feat;

    if (HEADS == 4) {
        float4 ad = ((const float4*)adst)[n];
        float m0 = -1e30f, m1 = -1e30f, m2 = -1e30f, m3 = -1e30f;
        float a0 = 0.f, a1 = 0.f, a2 = 0.f, a3 = 0.f;
        float s0 = 0.f, s1 = 0.f, s2 = 0.f, s3 = 0.f;
        for (int base = beg; base < end; base += 32) {
            int cnt = min(32, end - base);
            float l0 = -1e30f, l1 = -1e30f, l2 = -1e30f, l3 = -1e30f;
            int src = 0;
            if (lane < cnt) {
                src = g_csr[base + lane];
                float4 a = ((const float4*)asrc)[src];
                l0 = lrelu(a.x + ad.x);
                l1 = lrelu(a.y + ad.y);
                l2 = lrelu(a.z + ad.z);
                l3 = lrelu(a.w + ad.w);
            }
            float c0 = l0, c1 = l1, c2 = l2, c3 = l3;
            #pragma unroll
            for (int off = 16; off >= 1; off >>= 1) {
                c0 = fmaxf(c0, __shfl_xor_sync(0xffffffffu, c0, off));
                c1 = fmaxf(c1, __shfl_xor_sync(0xffffffffu, c1, off));
                c2 = fmaxf(c2, __shfl_xor_sync(0xffffffffu, c2, off));
                c3 = fmaxf(c3, __shfl_xor_sync(0xffffffffu, c3, off));
            }
            float nm0 = fmaxf(m0, c0), nm1 = fmaxf(m1, c1);
            float nm2 = fmaxf(m2, c2), nm3 = fmaxf(m3, c3);
            float f0 = __expf(m0 - nm0), f1 = __expf(m1 - nm1);
            float f2 = __expf(m2 - nm2), f3 = __expf(m3 - nm3);
            a0 *= f0; a1 *= f1; a2 *= f2; a3 *= f3;
            s0 *= f0; s1 *= f1; s2 *= f2; s3 *= f3;
            m0 = nm0; m1 = nm1; m2 = nm2; m3 = nm3;
            if (lane < cnt) {
                float4 wv;
                wv.x = __expf(l0 - m0);
                wv.y = __expf(l1 - m1);
                wv.z = __expf(l2 - m2);
                wv.w = __expf(l3 - m3);
                s_w4[wid][lane] = wv;
                s_src[wid][lane] = src;
            }
            __syncwarp();
            for (int i = 0; i < cnt; ++i) {
                float4 wv = s_w4[wid][i];
                int si = s_src[wid][i];
                float4 v = feat4[(size_t)si * 32 + lane];
                a0 += wv.x * v.x; a1 += wv.y * v.y; a2 += wv.z * v.z; a3 += wv.w * v.w;
                s0 += wv.x; s1 += wv.y; s2 += wv.z; s3 += wv.w;
            }
            __syncwarp();
        }
        float o0 = a0 / s0 + bias[lane];
        float o1 = a1 / s1 + bias[32 + lane];
        float o2 = a2 / s2 + bias[64 + lane];
        float o3 = a3 / s3 + bias[96 + lane];
        o0 = (o0 > 0.f) ? o0 : (__expf(o0) - 1.f);
        o1 = (o1 > 0.f) ? o1 : (__expf(o1) - 1.f);
        o2 = (o2 > 0.f) ? o2 : (__expf(o2) - 1.f);
        o3 = (o3 > 0.f) ? o3 : (__expf(o3) - 1.f);
        size_t b = (size_t)n * 128;
        out[b + lane] = o0;
        out[b + 32 + lane] = o1;
        out[b + 64 + lane] = o2;
        out[b + 96 + lane] = o3;
    } else {
        float* s_wf = (float*)&s_w4[wid][0];
        float ad = adst[n];
        float m = -1e30f, acc = 0.f, ssum = 0.f;
        for (int base = beg; base < end; base += 32) {
            int cnt = min(32, end - base);
            float l = -1e30f;
            int src = 0;
            if (lane < cnt) {
                src = g_csr[base + lane];
                l = lrelu(asrc[src] + ad);
            }
            float c = l;
            #pragma unroll
            for (int off = 16; off >= 1; off >>= 1)
                c = fmaxf(c, __shfl_xor_sync(0xffffffffu, c, off));
            float nm = fmaxf(m, c);
            float f = __expf(m - nm);
            acc *= f; ssum *= f;
            m = nm;
            if (lane < cnt) {
                s_wf[lane] = __expf(l - m);
                s_src[wid][lane] = src;
            }
            __syncwarp();
            for (int i = 0; i < cnt; ++i) {
                float wi = s_wf[i];
                int si = s_src[wid][i];
                acc += wi * feat[(size_t)si * 32 + lane];
                ssum += wi;
            }
            __syncwarp();
        }
        float o = acc / ssum + bias[lane];
        o = 1.f / (1.f + __expf(-o));
        out[(size_t)n * 32 + lane] = o;
    }
}

// ---------------- host launcher (single stream, capture-safe) ----------------
extern "C" void kernel_launch(void* const* d_in, const int* in_sizes, int n_in,
                              void* d_out, int out_size) {
    const float* x = (const float*)d_in[0];
    const void* ei = d_in[1];
    const float* W[4]  = {(const float*)d_in[2], (const float*)d_in[6],
                          (const float*)d_in[10], (const float*)d_in[14]};
    const float* As[4] = {(const float*)d_in[3], (const float*)d_in[7],
                          (const float*)d_in[11], (const float*)d_in[15]};
    const float* Ad[4] = {(const float*)d_in[4], (const float*)d_in[8],
                          (const float*)d_in[12], (const float*)d_in[16]};
    const float* B[4]  = {(const float*)d_in[5], (const float*)d_in[9],
                          (const float*)d_in[13], (const float*)d_in[17]};
    float* out = (float*)d_out;

    float *p_h0, *p_h1, *p_asrc, *p_adst;
    cudaGetSymbolAddress((void**)&p_h0, g_h0);
    cudaGetSymbolAddress((void**)&p_h1, g_h1);
    cudaGetSymbolAddress((void**)&p_asrc, g_asrc);
    cudaGetSymbolAddress((void**)&p_adst, g_adst);

    constexpr int SMEM_TC = 1024 + (2 * 128 * XP2) * 4 + 16 * BQP * 16;  // 1024+36864+33280 = 71168
    constexpr int SMEM_SMALL = (128 * 32 + 64 * 132) * 4;                // 50176 B
    cudaFuncSetAttribute(gemm_tc_kernel,
                         cudaFuncAttributeMaxDynamicSharedMemorySize, SMEM_TC);
    cudaFuncSetAttribute(gemm32_kernel,
                         cudaFuncAttributeMaxDynamicSharedMemorySize, SMEM_SMALL);

    const int GTC = (NN + 127) / 128;  // 391
    const int GB = (NN + 63) / 64;     // 782
    const int AB = (NN + 7) / 8;       // 6250

    // CSR build, with layer-1 GEMM (CSR-independent) slotted at launch index 3
    // so the ncu capture lands on it.
    detect_kernel<<<1, 256>>>((const int*)ei);                             // 0
    init_deg_kernel<<<(NN + 255) / 256, 256>>>();                          // 1
    hist_kernel<<<(EE + 255) / 256, 256>>>(ei);                            // 2
    gemm_tc_kernel<<<GTC, 512, SMEM_TC>>>(x, W[0], As[0], Ad[0],           // 3 (profiled)
                                          p_h1, p_asrc, p_adst);
    scan_local_kernel<<<NBS, 1024>>>();                                    // 4
    scan_block_kernel<<<1, 32>>>();                                        // 5
    scan_add_kernel<<<NBS, 1024>>>();                                      // 6
    scatter_kernel<<<(EE + 255) / 256, 256>>>(ei);                         // 7

    // layer 1 aggregation
    agg_kernel<4, 0><<<AB, 256>>>(p_h1, p_asrc, p_adst, B[0], p_h0);
    // layer 2
    gemm_tc_kernel<<<GTC, 512, SMEM_TC>>>(p_h0, W[1], As[1], Ad[1], p_h1, p_asrc, p_adst);
    agg_kernel<4, 0><<<AB, 256>>>(p_h1, p_asrc, p_adst, B[1], p_h0);
    // layer 3
    gemm_tc_kernel<<<GTC, 512, SMEM_TC>>>(p_h0, W[2], As[2], Ad[2], p_h1, p_asrc, p_adst);
    agg_kernel<4, 0><<<AB, 256>>>(p_h1, p_asrc, p_adst, B[2], p_h0);
    // layer 4 (heads=1, 32 labels) -> sigmoid -> d_out
    gemm32_kernel<<<GB, 256, SMEM_SMALL>>>(p_h0, W[3], As[3], Ad[3], p_h1, p_asrc, p_adst);
    agg_kernel<1, 1><<<AB, 256>>>(p_h1, p_asrc, p_adst, B[3], out);
}

// round 13
// speedup vs baseline: 1.4175x; 1.2056x over previous
#include <cuda_runtime.h>
#include <cstdint>

#define NN 50000
#define EE 800000
#define NBS 49   // ceil(NN/1024)

typedef unsigned long long u64;

// ---------------- scratch (device globals; no allocation allowed) ----------------
__device__ __align__(16) float g_h0[(size_t)NN * 128];   // layer input features
__device__ __align__(16) float g_h1[(size_t)NN * 128];   // h = x@W (interleaved [N][32][4])
__device__ __align__(16) float g_asrc[NN * 4];
__device__ __align__(16) float g_adst[NN * 4];
__device__ int g_deg[NN];
__device__ int g_ptr[NN + 1];
__device__ int g_bsum[64];
__device__ int g_csr[EE + NN];
__device__ int g_is64;

// ---------------- tf32 helpers ----------------
__device__ __forceinline__ uint32_t f2tf(float x) {
    uint32_t u;
    asm("cvt.rna.tf32.f32 %0, %1;" : "=r"(u) : "f"(x));
    return u;
}
__device__ __forceinline__ void mma_tf32(float* c, const uint32_t* a, uint32_t b0, uint32_t b1) {
    asm volatile(
        "mma.sync.aligned.m16n8k8.row.col.f32.tf32.tf32.f32 "
        "{%0,%1,%2,%3}, {%4,%5,%6,%7}, {%8,%9}, {%0,%1,%2,%3};"
        : "+f"(c[0]), "+f"(c[1]), "+f"(c[2]), "+f"(c[3])
        : "r"(a[0]), "r"(a[1]), "r"(a[2]), "r"(a[3]), "r"(b0), "r"(b1));
}

// ---------------- CSR build ----------------
__global__ void detect_kernel(const int* __restrict__ e32) {
    __shared__ int any;
    if (threadIdx.x == 0) any = 0;
    __syncthreads();
    int local = 0;
    for (int i = threadIdx.x; i < 4096; i += blockDim.x)
        if (e32[2 * i + 1] != 0) local = 1;
    if (local) any = 1;
    __syncthreads();
    if (threadIdx.x == 0) g_is64 = (any == 0) ? 1 : 0;
}

__global__ void init_deg_kernel() {
    int n = blockIdx.x * blockDim.x + threadIdx.x;
    if (n < NN) g_deg[n] = 1;   // self loop
}

__global__ void hist_kernel(const void* __restrict__ ei) {
    int e = blockIdx.x * blockDim.x + threadIdx.x;
    if (e >= EE) return;
    int d = g_is64 ? (int)((const long long*)ei)[EE + e]
                   : ((const int*)ei)[EE + e];
    atomicAdd(&g_deg[d], 1);
}

__global__ void scan_local_kernel() {
    __shared__ int wsum[32];
    int t = threadIdx.x;
    int i = blockIdx.x * 1024 + t;
    int v = (i < NN) ? g_deg[i] : 0;
    int x = v;
    #pragma unroll
    for (int off = 1; off < 32; off <<= 1) {
        int y = __shfl_up_sync(0xffffffffu, x, off);
        if ((t & 31) >= off) x += y;
    }
    if ((t & 31) == 31) wsum[t >> 5] = x;
    __syncthreads();
    if (t < 32) {
        int w = wsum[t];
        #pragma unroll
        for (int off = 1; off < 32; off <<= 1) {
            int y = __shfl_up_sync(0xffffffffu, w, off);
            if (t >= off) w += y;
        }
        wsum[t] = w;
    }
    __syncthreads();
    int incl = x + ((t >= 32) ? wsum[(t >> 5) - 1] : 0);
    if (i < NN) g_ptr[i] = incl - v;
    if (t == 1023) g_bsum[blockIdx.x] = incl;
}

__global__ void scan_block_kernel() {   // 1 warp
    int t = threadIdx.x;
    int carry = 0;
    for (int base = 0; base < NBS; base += 32) {
        int v = (base + t < NBS) ? g_bsum[base + t] : 0;
        int x = v;
        #pragma unroll
        for (int off = 1; off < 32; off <<= 1) {
            int y = __shfl_up_sync(0xffffffffu, x, off);
            if (t >= off) x += y;
        }
        if (base + t < NBS) g_bsum[base + t] = carry + x - v;
        carry += __shfl_sync(0xffffffffu, x, 31);
    }
    if (t == 0) g_ptr[NN] = carry;
}

// finalize ptr AND place self-loop + reset cursor
__global__ void scan_add_kernel() {
    int i = blockIdx.x * 1024 + threadIdx.x;
    if (i < NN) {
        int p = g_ptr[i] + g_bsum[blockIdx.x];
        g_ptr[i] = p;
        g_csr[p] = i;    // self loop at slot 0
        g_deg[i] = 1;    // scatter cursor
    }
}

__global__ void scatter_kernel(const void* __restrict__ ei) {
    int e = blockIdx.x * blockDim.x + threadIdx.x;
    if (e >= EE) return;
    int s, d;
    if (g_is64) {
        s = (int)((const long long*)ei)[e];
        d = (int)((const long long*)ei)[EE + e];
    } else {
        s = ((const int*)ei)[e];
        d = ((const int*)ei)[EE + e];
    }
    int pos = atomicAdd(&g_deg[d], 1);
    g_csr[g_ptr[d] + pos] = s;
}

// ---------------- big GEMM via mma.sync tf32 (3xTF32), 512 threads, 2 blocks/SM ----------------
// BYTE-EXACT round-9 structure: K=128 in FOUR 32-wide chunks, scalar hi/lo smem.
#define XP2 36   // xs pitch (floats) for 32-wide K chunk
#define WP 136   // ws pitch (floats)
#define SP 132   // stage pitch (floats)

__global__ __launch_bounds__(512, 2)
void gemm_tc_kernel(const float* __restrict__ X, const float* __restrict__ W,
                    const float* __restrict__ att_s, const float* __restrict__ att_d,
                    float* __restrict__ H, float* __restrict__ asrc,
                    float* __restrict__ adst) {
    extern __shared__ char sh[];
    float* att_ss = (float*)sh;                        // 128 f
    float* att_ds = (float*)(sh + 512);                // 128 f
    uint32_t* xs_hi = (uint32_t*)(sh + 1024);          // [128][XP2]
    uint32_t* xs_lo = xs_hi + 128 * XP2;
    uint32_t* ws_hi = xs_lo + 128 * XP2;               // [32][WP]
    uint32_t* ws_lo = ws_hi + 32 * WP;
    float* stage = (float*)(sh + 1024);                // reused after mma

    int t = threadIdx.x;
    int lane = t & 31, wid = t >> 5;
    int g = lane >> 2, tig = lane & 3;
    int wm = wid >> 2, wn = wid & 3;
    int n0 = blockIdx.x * 128;

    if (t < 128) { att_ss[t] = att_s[t]; att_ds[t] = att_d[t]; }

    float acc[2][4][4];
    #pragma unroll
    for (int mt = 0; mt < 2; ++mt)
        #pragma unroll
        for (int nt = 0; nt < 4; ++nt)
            #pragma unroll
            for (int i = 0; i < 4; ++i) acc[mt][nt][i] = 0.f;

    for (int kc = 0; kc < 4; ++kc) {
        #pragma unroll 2
        for (int idx = t; idx < 128 * 8; idx += 512) {
            int r = idx >> 3, c4 = idx & 7;
            int n = n0 + r;
            float4 v = make_float4(0.f, 0.f, 0.f, 0.f);
            if (n < NN) v = ((const float4*)X)[(size_t)n * 32 + kc * 8 + c4];
            float e[4] = {v.x, v.y, v.z, v.w};
            #pragma unroll
            for (int j = 0; j < 4; ++j) {
                uint32_t hu = f2tf(e[j]);
                float lo = e[j] - __uint_as_float(hu);
                xs_hi[r * XP2 + c4 * 4 + j] = hu;
                xs_lo[r * XP2 + c4 * 4 + j] = f2tf(lo);
            }
        }
        #pragma unroll 2
        for (int idx = t; idx < 32 * 32; idx += 512) {
            int kr = idx >> 5, c4 = idx & 31;
            float4 v = ((const float4*)W)[(size_t)(kc * 32 + kr) * 32 + c4];
            float e[4] = {v.x, v.y, v.z, v.w};
            #pragma unroll
            for (int j = 0; j < 4; ++j) {
                uint32_t hu = f2tf(e[j]);
                float lo = e[j] - __uint_as_float(hu);
                ws_hi[kr * WP + c4 * 4 + j] = hu;
                ws_lo[kr * WP + c4 * 4 + j] = f2tf(lo);
            }
        }
        __syncthreads();

        const uint32_t* xa_h = xs_hi + (wm * 32 + g) * XP2 + tig;
        const uint32_t* xa_l = xs_lo + (wm * 32 + g) * XP2 + tig;
        const uint32_t* wb_h = ws_hi + tig * WP + wn * 32 + g;
        const uint32_t* wb_l = ws_lo + tig * WP + wn * 32 + g;

        #pragma unroll
        for (int ks = 0; ks < 4; ++ks) {
            uint32_t ah[2][4], al[2][4];
            #pragma unroll
            for (int mt = 0; mt < 2; ++mt) {
                int base = mt * 16 * XP2 + ks * 8;
                ah[mt][0] = xa_h[base];
                ah[mt][1] = xa_h[base + 8 * XP2];
                ah[mt][2] = xa_h[base + 4];
                ah[mt][3] = xa_h[base + 8 * XP2 + 4];
                al[mt][0] = xa_l[base];
                al[mt][1] = xa_l[base + 8 * XP2];
                al[mt][2] = xa_l[base + 4];
                al[mt][3] = xa_l[base + 8 * XP2 + 4];
            }
            #pragma unroll
            for (int nt = 0; nt < 4; ++nt) {
                int boff = ks * 8 * WP + nt * 8;
                uint32_t bh0 = wb_h[boff], bh1 = wb_h[boff + 4 * WP];
                uint32_t bl0 = wb_l[boff], bl1 = wb_l[boff + 4 * WP];
                #pragma unroll
                for (int mt = 0; mt < 2; ++mt) {
                    mma_tf32(acc[mt][nt], ah[mt], bh0, bh1);   // hi*hi
                    mma_tf32(acc[mt][nt], al[mt], bh0, bh1);   // lo*hi
                    mma_tf32(acc[mt][nt], ah[mt], bl0, bl1);   // hi*lo
                }
            }
        }
        __syncthreads();
    }

    // ---- epilogue: attention dots (warp covers exactly head wn) ----
    #pragma unroll
    for (int mt = 0; mt < 2; ++mt) {
        #pragma unroll
        for (int rh = 0; rh < 2; ++rh) {
            int n = n0 + wm * 32 + mt * 16 + g + rh * 8;
            float ps = 0.f, pd = 0.f;
            #pragma unroll
            for (int nt = 0; nt < 4; ++nt) {
                #pragma unroll
                for (int ci = 0; ci < 2; ++ci) {
                    int col = wn * 32 + nt * 8 + 2 * tig + ci;
                    float a = acc[mt][nt][rh * 2 + ci];
                    ps += a * att_ss[col];
                    pd += a * att_ds[col];
                }
            }
            #pragma unroll
            for (int off = 1; off <= 2; off <<= 1) {
                ps += __shfl_xor_sync(0xffffffffu, ps, off);
                pd += __shfl_xor_sync(0xffffffffu, pd, off);
            }
            if (tig == 0 && n < NN) {
                asrc[n * 4 + wn] = ps;
                adst[n * 4 + wn] = pd;
            }
        }
    }

    // ---- stage accs to smem, then interleaved H store ----
    #pragma unroll
    for (int mt = 0; mt < 2; ++mt) {
        int rbase = wm * 32 + mt * 16 + g;
        #pragma unroll
        for (int nt = 0; nt < 4; ++nt) {
            int col = wn * 32 + nt * 8 + 2 * tig;
            stage[rbase * SP + col] = acc[mt][nt][0];
            stage[rbase * SP + col + 1] = acc[mt][nt][1];
            stage[(rbase + 8) * SP + col] = acc[mt][nt][2];
            stage[(rbase + 8) * SP + col + 1] = acc[mt][nt][3];
        }
    }
    __syncthreads();
    #pragma unroll 2
    for (int idx = t; idx < 128 * 32; idx += 512) {
        int r = idx >> 5, fc = idx & 31;
        int n = n0 + r;
        if (n < NN) {
            const float* sr = stage + r * SP;
            ((float4*)H)[(size_t)n * 32 + fc] =
                make_float4(sr[fc], sr[32 + fc], sr[64 + fc], sr[96 + fc]);
        }
    }
}

// ---------------- layer-4 GEMM via mma.sync tf32 (3xTF32): 256 rows x 32 cols ----------------
// 8 warps (wm=wid), all warps cover all 32 cols (wn=0). K=128 in four 32-chunks.
#define WP32 40   // B pitch (floats): 32 used + 8 pad -> phase addr (8*tig+g) mod 32 distinct
#define SP32 36   // stage pitch (floats)

__global__ __launch_bounds__(256, 2)
void gemm32_tc_kernel(const float* __restrict__ X, const float* __restrict__ W,
                      const float* __restrict__ att_s, const float* __restrict__ att_d,
                      float* __restrict__ H, float* __restrict__ asrc,
                      float* __restrict__ adst) {
    extern __shared__ char sh[];
    float* att_ss = (float*)sh;                        // 32 f
    float* att_ds = (float*)(sh + 512);                // 32 f
    uint32_t* xs_hi = (uint32_t*)(sh + 1024);          // [256][XP2]
    uint32_t* xs_lo = xs_hi + 256 * XP2;
    uint32_t* ws_hi = xs_lo + 256 * XP2;               // [32][WP32]
    uint32_t* ws_lo = ws_hi + 32 * WP32;
    float* stage = (float*)(sh + 1024);                // reused after mma

    int t = threadIdx.x;
    int lane = t & 31, wid = t >> 5;
    int g = lane >> 2, tig = lane & 3;
    int wm = wid;                                      // 8 warps x 32 rows = 256 rows
    int n0 = blockIdx.x * 256;

    if (t < 32) { att_ss[t] = att_s[t]; att_ds[t] = att_d[t]; }

    float acc[2][4][4];
    #pragma unroll
    for (int mt = 0; mt < 2; ++mt)
        #pragma unroll
        for (int nt = 0; nt < 4; ++nt)
            #pragma unroll
            for (int i = 0; i < 4; ++i) acc[mt][nt][i] = 0.f;

    for (int kc = 0; kc < 4; ++kc) {
        // X rows (256 x 8 float4)
        #pragma unroll 4
        for (int idx = t; idx < 256 * 8; idx += 256) {
            int r = idx >> 3, c4 = idx & 7;
            int n = n0 + r;
            float4 v = make_float4(0.f, 0.f, 0.f, 0.f);
            if (n < NN) v = ((const float4*)X)[(size_t)n * 32 + kc * 8 + c4];
            float e[4] = {v.x, v.y, v.z, v.w};
            #pragma unroll
            for (int j = 0; j < 4; ++j) {
                uint32_t hu = f2tf(e[j]);
                float lo = e[j] - __uint_as_float(hu);
                xs_hi[r * XP2 + c4 * 4 + j] = hu;
                xs_lo[r * XP2 + c4 * 4 + j] = f2tf(lo);
            }
        }
        // W rows (32 k x 8 float4) — W is [128][32]
        if (t < 256) {
            int kr = t >> 3, c4 = t & 7;
            if (kr < 32) {
                float4 v = ((const float4*)W)[(size_t)(kc * 32 + kr) * 8 + c4];
                float e[4] = {v.x, v.y, v.z, v.w};
                #pragma unroll
                for (int j = 0; j < 4; ++j) {
                    uint32_t hu = f2tf(e[j]);
                    float lo = e[j] - __uint_as_float(hu);
                    ws_hi[kr * WP32 + c4 * 4 + j] = hu;
                    ws_lo[kr * WP32 + c4 * 4 + j] = f2tf(lo);
                }
            }
        }
        __syncthreads();

        const uint32_t* xa_h = xs_hi + (wm * 32 + g) * XP2 + tig;
        const uint32_t* xa_l = xs_lo + (wm * 32 + g) * XP2 + tig;
        const uint32_t* wb_h = ws_hi + tig * WP32 + g;
        const uint32_t* wb_l = ws_lo + tig * WP32 + g;

        #pragma unroll
        for (int ks = 0; ks < 4; ++ks) {
            uint32_t ah[2][4], al[2][4];
            #pragma unroll
            for (int mt = 0; mt < 2; ++mt) {
                int base = mt * 16 * XP2 + ks * 8;
                ah[mt][0] = xa_h[base];
                ah[mt][1] = xa_h[base + 8 * XP2];
                ah[mt][2] = xa_h[base + 4];
                ah[mt][3] = xa_h[base + 8 * XP2 + 4];
                al[mt][0] = xa_l[base];
                al[mt][1] = xa_l[base + 8 * XP2];
                al[mt][2] = xa_l[base + 4];
                al[mt][3] = xa_l[base + 8 * XP2 + 4];
            }
            #pragma unroll
            for (int nt = 0; nt < 4; ++nt) {
                int boff = ks * 8 * WP32 + nt * 8;
                uint32_t bh0 = wb_h[boff], bh1 = wb_h[boff + 4 * WP32];
                uint32_t bl0 = wb_l[boff], bl1 = wb_l[boff + 4 * WP32];
                #pragma unroll
                for (int mt = 0; mt < 2; ++mt) {
                    mma_tf32(acc[mt][nt], ah[mt], bh0, bh1);
                    mma_tf32(acc[mt][nt], al[mt], bh0, bh1);
                    mma_tf32(acc[mt][nt], ah[mt], bl0, bl1);
                }
            }
        }
        __syncthreads();
    }

    // ---- epilogue: attention dots (single head) ----
    #pragma unroll
    for (int mt = 0; mt < 2; ++mt) {
        #pragma unroll
        for (int rh = 0; rh < 2; ++rh) {
            int n = n0 + wm * 32 + mt * 16 + g + rh * 8;
            float ps = 0.f, pd = 0.f;
            #pragma unroll
            for (int nt = 0; nt < 4; ++nt) {
                #pragma unroll
                for (int ci = 0; ci < 2; ++ci) {
                    int col = nt * 8 + 2 * tig + ci;
                    float a = acc[mt][nt][rh * 2 + ci];
                    ps += a * att_ss[col];
                    pd += a * att_ds[col];
                }
            }
            #pragma unroll
            for (int off = 1; off <= 2; off <<= 1) {
                ps += __shfl_xor_sync(0xffffffffu, ps, off);
                pd += __shfl_xor_sync(0xffffffffu, pd, off);
            }
            if (tig == 0 && n < NN) {
                asrc[n] = ps;
                adst[n] = pd;
            }
        }
    }

    // ---- stage + coalesced H store (plain [n][32] layout) ----
    #pragma unroll
    for (int mt = 0; mt < 2; ++mt) {
        int rbase = wm * 32 + mt * 16 + g;
        #pragma unroll
        for (int nt = 0; nt < 4; ++nt) {
            int col = nt * 8 + 2 * tig;
            stage[rbase * SP32 + col] = acc[mt][nt][0];
            stage[rbase * SP32 + col + 1] = acc[mt][nt][1];
            stage[(rbase + 8) * SP32 + col] = acc[mt][nt][2];
            stage[(rbase + 8) * SP32 + col + 1] = acc[mt][nt][3];
        }
    }
    __syncthreads();
    #pragma unroll 4
    for (int idx = t; idx < 256 * 8; idx += 256) {
        int r = idx >> 3, fc = idx & 7;
        int n = n0 + r;
        if (n < NN)
            ((float4*)H)[(size_t)n * 8 + fc] = *(const float4*)(stage + r * SP32 + fc * 4);
    }
}

// ---------------- per-node ONLINE softmax + aggregation (single edge pass) ----------------
__device__ __forceinline__ float lrelu(float v) { return fmaxf(v, 0.2f * v); }

template <int HEADS, int ACT>   // ACT: 0 = ELU, 1 = sigmoid
__launch_bounds__(256)
__global__ void agg_kernel(const float* __restrict__ feat,
                           const float* __restrict__ asrc, const float* __restrict__ adst,
                           const float* __restrict__ bias, float* __restrict__ out) {
    __shared__ float4 s_w4[8][32];
    __shared__ int s_src[8][32];
    int wid = threadIdx.x >> 5;
    int lane = threadIdx.x & 31;
    int n = blockIdx.x * 8 + wid;
    if (n >= NN) return;
    int beg = g_ptr[n], end = g_ptr[n + 1];
    const float4* feat4 = (const float4*)feat;

    if (HEADS == 4) {
        float4 ad = ((const float4*)adst)[n];
        float m0 = -1e30f, m1 = -1e30f, m2 = -1e30f, m3 = -1e30f;
        float a0 = 0.f, a1 = 0.f, a2 = 0.f, a3 = 0.f;
        float s0 = 0.f, s1 = 0.f, s2 = 0.f, s3 = 0.f;
        for (int base = beg; base < end; base += 32) {
            int cnt = min(32, end - base);
            float l0 = -1e30f, l1 = -1e30f, l2 = -1e30f, l3 = -1e30f;
            int src = 0;
            if (lane < cnt) {
                src = g_csr[base + lane];
                float4 a = ((const float4*)asrc)[src];
                l0 = lrelu(a.x + ad.x);
                l1 = lrelu(a.y + ad.y);
                l2 = lrelu(a.z + ad.z);
                l3 = lrelu(a.w + ad.w);
            }
            float c0 = l0, c1 = l1, c2 = l2, c3 = l3;
            #pragma unroll
            for (int off = 16; off >= 1; off >>= 1) {
                c0 = fmaxf(c0, __shfl_xor_sync(0xffffffffu, c0, off));
                c1 = fmaxf(c1, __shfl_xor_sync(0xffffffffu, c1, off));
                c2 = fmaxf(c2, __shfl_xor_sync(0xffffffffu, c2, off));
                c3 = fmaxf(c3, __shfl_xor_sync(0xffffffffu, c3, off));
            }
            float nm0 = fmaxf(m0, c0), nm1 = fmaxf(m1, c1);
            float nm2 = fmaxf(m2, c2), nm3 = fmaxf(m3, c3);
            float f0 = __expf(m0 - nm0), f1 = __expf(m1 - nm1);
            float f2 = __expf(m2 - nm2), f3 = __expf(m3 - nm3);
            a0 *= f0; a1 *= f1; a2 *= f2; a3 *= f3;
            s0 *= f0; s1 *= f1; s2 *= f2; s3 *= f3;
            m0 = nm0; m1 = nm1; m2 = nm2; m3 = nm3;
            if (lane < cnt) {
                float4 wv;
                wv.x = __expf(l0 - m0);
                wv.y = __expf(l1 - m1);
                wv.z = __expf(l2 - m2);
                wv.w = __expf(l3 - m3);
                s_w4[wid][lane] = wv;
                s_src[wid][lane] = src;
            }
            __syncwarp();
            for (int i = 0; i < cnt; ++i) {
                float4 wv = s_w4[wid][i];
                int si = s_src[wid][i];
                float4 v = feat4[(size_t)si * 32 + lane];
                a0 += wv.x * v.x; a1 += wv.y * v.y; a2 += wv.z * v.z; a3 += wv.w * v.w;
                s0 += wv.x; s1 += wv.y; s2 += wv.z; s3 += wv.w;
            }
            __syncwarp();
        }
        float o0 = a0 / s0 + bias[lane];
        float o1 = a1 / s1 + bias[32 + lane];
        float o2 = a2 / s2 + bias[64 + lane];
        float o3 = a3 / s3 + bias[96 + lane];
        o0 = (o0 > 0.f) ? o0 : (__expf(o0) - 1.f);
        o1 = (o1 > 0.f) ? o1 : (__expf(o1) - 1.f);
        o2 = (o2 > 0.f) ? o2 : (__expf(o2) - 1.f);
        o3 = (o3 > 0.f) ? o3 : (__expf(o3) - 1.f);
        size_t b = (size_t)n * 128;
        out[b + lane] = o0;
        out[b + 32 + lane] = o1;
        out[b + 64 + lane] = o2;
        out[b + 96 + lane] = o3;
    } else {
        float* s_wf = (float*)&s_w4[wid][0];
        float ad = adst[n];
        float m = -1e30f, acc = 0.f, ssum = 0.f;
        for (int base = beg; base < end; base += 32) {
            int cnt = min(32, end - base);
            float l = -1e30f;
            int src = 0;
            if (lane < cnt) {
                src = g_csr[base + lane];
                l = lrelu(asrc[src] + ad);
            }
            float c = l;
            #pragma unroll
            for (int off = 16; off >= 1; off >>= 1)
                c = fmaxf(c, __shfl_xor_sync(0xffffffffu, c, off));
            float nm = fmaxf(m, c);
            float f = __expf(m - nm);
            acc *= f; ssum *= f;
            m = nm;
            if (lane < cnt) {
                s_wf[lane] = __expf(l - m);
                s_src[wid][lane] = src;
            }
            __syncwarp();
            for (int i = 0; i < cnt; ++i) {
                float wi = s_wf[i];
                int si = s_src[wid][i];
                acc += wi * feat[(size_t)si * 32 + lane];
                ssum += wi;
            }
            __syncwarp();
        }
        float o = acc / ssum + bias[lane];
        o = 1.f / (1.f + __expf(-o));
        out[(size_t)n * 32 + lane] = o;
    }
}

// ---------------- host launcher (single stream, capture-safe) ----------------
extern "C" void kernel_launch(void* const* d_in, const int* in_sizes, int n_in,
                              void* d_out, int out_size) {
    const float* x = (const float*)d_in[0];
    const void* ei = d_in[1];
    const float* W[4]  = {(const float*)d_in[2], (const float*)d_in[6],
                          (const float*)d_in[10], (const float*)d_in[14]};
    const float* As[4] = {(const float*)d_in[3], (const float*)d_in[7],
                          (const float*)d_in[11], (const float*)d_in[15]};
    const float* Ad[4] = {(const float*)d_in[4], (const float*)d_in[8],
                          (const float*)d_in[12], (const float*)d_in[16]};
    const float* B[4]  = {(const float*)d_in[5], (const float*)d_in[9],
                          (const float*)d_in[13], (const float*)d_in[17]};
    float* out = (float*)d_out;

    float *p_h0, *p_h1, *p_asrc, *p_adst;
    cudaGetSymbolAddress((void**)&p_h0, g_h0);
    cudaGetSymbolAddress((void**)&p_h1, g_h1);
    cudaGetSymbolAddress((void**)&p_asrc, g_asrc);
    cudaGetSymbolAddress((void**)&p_adst, g_adst);

    constexpr int SMEM_TC = 1024 + (2 * 128 * XP2 + 2 * 32 * WP) * 4;    // 72704 B
    constexpr int SMEM_32 = 1024 + (2 * 256 * XP2 + 2 * 32 * WP32) * 4;  // 1024+73728+10240 = 84992 B
    cudaFuncSetAttribute(gemm_tc_kernel,
                         cudaFuncAttributeMaxDynamicSharedMemorySize, SMEM_TC);
    cudaFuncSetAttribute(gemm32_tc_kernel,
                         cudaFuncAttributeMaxDynamicSharedMemorySize, SMEM_32);

    const int GTC = (NN + 127) / 128;   // 391
    const int G32 = (NN + 255) / 256;   // 196
    const int AB = (NN + 7) / 8;        // 6250

    // CSR build, with layer-1 GEMM (CSR-independent) slotted at launch index 3
    // so the ncu capture lands on it.
    detect_kernel<<<1, 256>>>((const int*)ei);                             // 0
    init_deg_kernel<<<(NN + 255) / 256, 256>>>();                          // 1
    hist_kernel<<<(EE + 255) / 256, 256>>>(ei);                            // 2
    gemm_tc_kernel<<<GTC, 512, SMEM_TC>>>(x, W[0], As[0], Ad[0],           // 3 (profiled)
                                          p_h1, p_asrc, p_adst);
    scan_local_kernel<<<NBS, 1024>>>();                                    // 4
    scan_block_kernel<<<1, 32>>>();                                        // 5
    scan_add_kernel<<<NBS, 1024>>>();                                      // 6
    scatter_kernel<<<(EE + 255) / 256, 256>>>(ei);                         // 7

    // layer 1 aggregation
    agg_kernel<4, 0><<<AB, 256>>>(p_h1, p_asrc, p_adst, B[0], p_h0);
    // layer 2
    gemm_tc_kernel<<<GTC, 512, SMEM_TC>>>(p_h0, W[1], As[1], Ad[1], p_h1, p_asrc, p_adst);
    agg_kernel<4, 0><<<AB, 256>>>(p_h1, p_asrc, p_adst, B[1], p_h0);
    // layer 3
    gemm_tc_kernel<<<GTC, 512, SMEM_TC>>>(p_h0, W[2], As[2], Ad[2], p_h1, p_asrc, p_adst);
    agg_kernel<4, 0><<<AB, 256>>>(p_h1, p_asrc, p_adst, B[2], p_h0);
    // layer 4 (heads=1, 32 labels) -> sigmoid -> d_out
    gemm32_tc_kernel<<<G32, 256, SMEM_32>>>(p_h0, W[3], As[3], Ad[3], p_h1, p_asrc, p_adst);
    agg_kernel<1, 1><<<AB, 256>>>(p_h1, p_asrc, p_adst, B[3], out);
}

// round 14
// speedup vs baseline: 1.4178x; 1.0002x over previous
#include <cuda_runtime.h>
#include <cstdint>

#define NN 50000
#define EE 800000
#define NBS 49   // ceil(NN/1024)

// ---------------- scratch (device globals; no allocation allowed) ----------------
__device__ __align__(16) float g_h0[(size_t)NN * 128];   // layer input features
__device__ __align__(16) float g_h1[(size_t)NN * 128];   // h = x@W (interleaved [N][32][4])
__device__ __align__(16) float g_asrc[NN * 4];
__device__ __align__(16) float g_adst[NN * 4];
__device__ int g_deg[NN];
__device__ int g_ptr[NN + 1];
__device__ int g_bsum[64];
__device__ int g_csr[EE + NN];
__device__ int g_is64;

// ---------------- tf32 helpers ----------------
__device__ __forceinline__ uint32_t f2tf(float x) {
    uint32_t u;
    asm("cvt.rna.tf32.f32 %0, %1;" : "=r"(u) : "f"(x));
    return u;
}
__device__ __forceinline__ void mma_tf32(float* c, const uint32_t* a, uint32_t b0, uint32_t b1) {
    asm volatile(
        "mma.sync.aligned.m16n8k8.row.col.f32.tf32.tf32.f32 "
        "{%0,%1,%2,%3}, {%4,%5,%6,%7}, {%8,%9}, {%0,%1,%2,%3};"
        : "+f"(c[0]), "+f"(c[1]), "+f"(c[2]), "+f"(c[3])
        : "r"(a[0]), "r"(a[1]), "r"(a[2]), "r"(a[3]), "r"(b0), "r"(b1));
}

// ---------------- CSR build ----------------
// fused: degree init (all blocks) + int-width detect (block 0)
__global__ void detect_init_kernel(const int* __restrict__ e32) {
    int n = blockIdx.x * blockDim.x + threadIdx.x;
    if (n < NN) g_deg[n] = 1;   // self loop
    if (blockIdx.x == 0) {
        __shared__ int any;
        if (threadIdx.x == 0) any = 0;
        __syncthreads();
        int local = 0;
        for (int i = threadIdx.x; i < 4096; i += blockDim.x)
            if (e32[2 * i + 1] != 0) local = 1;
        if (local) any = 1;
        __syncthreads();
        if (threadIdx.x == 0) g_is64 = (any == 0) ? 1 : 0;
    }
}

__global__ void hist_kernel(const void* __restrict__ ei) {
    int e = blockIdx.x * blockDim.x + threadIdx.x;
    if (e >= EE) return;
    int d = g_is64 ? (int)((const long long*)ei)[EE + e]
                   : ((const int*)ei)[EE + e];
    atomicAdd(&g_deg[d], 1);
}

__global__ void scan_local_kernel() {
    __shared__ int wsum[32];
    int t = threadIdx.x;
    int i = blockIdx.x * 1024 + t;
    int v = (i < NN) ? g_deg[i] : 0;
    int x = v;
    #pragma unroll
    for (int off = 1; off < 32; off <<= 1) {
        int y = __shfl_up_sync(0xffffffffu, x, off);
        if ((t & 31) >= off) x += y;
    }
    if ((t & 31) == 31) wsum[t >> 5] = x;
    __syncthreads();
    if (t < 32) {
        int w = wsum[t];
        #pragma unroll
        for (int off = 1; off < 32; off <<= 1) {
            int y = __shfl_up_sync(0xffffffffu, w, off);
            if (t >= off) w += y;
        }
        wsum[t] = w;
    }
    __syncthreads();
    int incl = x + ((t >= 32) ? wsum[(t >> 5) - 1] : 0);
    if (i < NN) g_ptr[i] = incl - v;
    if (t == 1023) g_bsum[blockIdx.x] = incl;
}

// finalize ptr (block prefix computed redundantly per block) + self-loop + cursor
__global__ void scan_add_kernel() {
    __shared__ int s_pref;
    int t = threadIdx.x;
    if (t < 32) {
        int carry = 0;
        for (int base = 0; base < NBS; base += 32) {
            int v = (base + t < NBS) ? g_bsum[base + t] : 0;
            int x = v;
            #pragma unroll
            for (int off = 1; off < 32; off <<= 1) {
                int y = __shfl_up_sync(0xffffffffu, x, off);
                if (t >= off) x += y;
            }
            if (base + t == (int)blockIdx.x) s_pref = carry + x - v;
            carry += __shfl_sync(0xffffffffu, x, 31);
        }
        if (blockIdx.x == 0 && t == 0) g_ptr[NN] = carry;
    }
    __syncthreads();
    int i = blockIdx.x * 1024 + t;
    if (i < NN) {
        int p = g_ptr[i] + s_pref;
        g_ptr[i] = p;
        g_csr[p] = i;    // self loop at slot 0
        g_deg[i] = 1;    // scatter cursor
    }
}

__global__ void scatter_kernel(const void* __restrict__ ei) {
    int e = blockIdx.x * blockDim.x + threadIdx.x;
    if (e >= EE) return;
    int s, d;
    if (g_is64) {
        s = (int)((const long long*)ei)[e];
        d = (int)((const long long*)ei)[EE + e];
    } else {
        s = ((const int*)ei)[e];
        d = ((const int*)ei)[EE + e];
    }
    int pos = atomicAdd(&g_deg[d], 1);
    g_csr[g_ptr[d] + pos] = s;
}

// ---------------- big GEMM via mma.sync tf32 (3xTF32), 512 threads, 2 blocks/SM ----------------
#define XP2 36   // xs pitch (floats) for 32-wide K chunk
#define WP 136   // ws pitch (floats)
#define SP 132   // stage pitch (floats)

__global__ __launch_bounds__(512, 2)
void gemm_tc_kernel(const float* __restrict__ X, const float* __restrict__ W,
                    const float* __restrict__ att_s, const float* __restrict__ att_d,
                    float* __restrict__ H, float* __restrict__ asrc,
                    float* __restrict__ adst) {
    extern __shared__ char sh[];
    float* att_ss = (float*)sh;                        // 128 f
    float* att_ds = (float*)(sh + 512);                // 128 f
    uint32_t* xs_hi = (uint32_t*)(sh + 1024);          // [128][XP2]
    uint32_t* xs_lo = xs_hi + 128 * XP2;
    uint32_t* ws_hi = xs_lo + 128 * XP2;               // [32][WP]
    uint32_t* ws_lo = ws_hi + 32 * WP;
    float* stage = (float*)(sh + 1024);                // reused after mma

    int t = threadIdx.x;
    int lane = t & 31, wid = t >> 5;
    int g = lane >> 2, tig = lane & 3;
    int wm = wid >> 2, wn = wid & 3;
    int n0 = blockIdx.x * 128;

    if (t < 128) { att_ss[t] = att_s[t]; att_ds[t] = att_d[t]; }

    float acc[2][4][4];
    #pragma unroll
    for (int mt = 0; mt < 2; ++mt)
        #pragma unroll
        for (int nt = 0; nt < 4; ++nt)
            #pragma unroll
            for (int i = 0; i < 4; ++i) acc[mt][nt][i] = 0.f;

    for (int kc = 0; kc < 4; ++kc) {
        #pragma unroll 2
        for (int idx = t; idx < 128 * 8; idx += 512) {
            int r = idx >> 3, c4 = idx & 7;
            int n = n0 + r;
            float4 v = make_float4(0.f, 0.f, 0.f, 0.f);
            if (n < NN) v = ((const float4*)X)[(size_t)n * 32 + kc * 8 + c4];
            float e[4] = {v.x, v.y, v.z, v.w};
            #pragma unroll
            for (int j = 0; j < 4; ++j) {
                uint32_t hu = f2tf(e[j]);
                float lo = e[j] - __uint_as_float(hu);
                xs_hi[r * XP2 + c4 * 4 + j] = hu;
                xs_lo[r * XP2 + c4 * 4 + j] = f2tf(lo);
            }
        }
        #pragma unroll 2
        for (int idx = t; idx < 32 * 32; idx += 512) {
            int kr = idx >> 5, c4 = idx & 31;
            float4 v = ((const float4*)W)[(size_t)(kc * 32 + kr) * 32 + c4];
            float e[4] = {v.x, v.y, v.z, v.w};
            #pragma unroll
            for (int j = 0; j < 4; ++j) {
                uint32_t hu = f2tf(e[j]);
                float lo = e[j] - __uint_as_float(hu);
                ws_hi[kr * WP + c4 * 4 + j] = hu;
                ws_lo[kr * WP + c4 * 4 + j] = f2tf(lo);
            }
        }
        __syncthreads();

        const uint32_t* xa_h = xs_hi + (wm * 32 + g) * XP2 + tig;
        const uint32_t* xa_l = xs_lo + (wm * 32 + g) * XP2 + tig;
        const uint32_t* wb_h = ws_hi + tig * WP + wn * 32 + g;
        const uint32_t* wb_l = ws_lo + tig * WP + wn * 32 + g;

        #pragma unroll
        for (int ks = 0; ks < 4; ++ks) {
            uint32_t ah[2][4], al[2][4];
            #pragma unroll
            for (int mt = 0; mt < 2; ++mt) {
                int base = mt * 16 * XP2 + ks * 8;
                ah[mt][0] = xa_h[base];
                ah[mt][1] = xa_h[base + 8 * XP2];
                ah[mt][2] = xa_h[base + 4];
                ah[mt][3] = xa_h[base + 8 * XP2 + 4];
                al[mt][0] = xa_l[base];
                al[mt][1] = xa_l[base + 8 * XP2];
                al[mt][2] = xa_l[base + 4];
                al[mt][3] = xa_l[base + 8 * XP2 + 4];
            }
            #pragma unroll
            for (int nt = 0; nt < 4; ++nt) {
                int boff = ks * 8 * WP + nt * 8;
                uint32_t bh0 = wb_h[boff], bh1 = wb_h[boff + 4 * WP];
                uint32_t bl0 = wb_l[boff], bl1 = wb_l[boff + 4 * WP];
                #pragma unroll
                for (int mt = 0; mt < 2; ++mt) {
                    mma_tf32(acc[mt][nt], ah[mt], bh0, bh1);   // hi*hi
                    mma_tf32(acc[mt][nt], al[mt], bh0, bh1);   // lo*hi
                    mma_tf32(acc[mt][nt], ah[mt], bl0, bl1);   // hi*lo
                }
            }
        }
        __syncthreads();
    }

    // ---- epilogue: attention dots (warp covers exactly head wn) ----
    #pragma unroll
    for (int mt = 0; mt < 2; ++mt) {
        #pragma unroll
        for (int rh = 0; rh < 2; ++rh) {
            int n = n0 + wm * 32 + mt * 16 + g + rh * 8;
            float ps = 0.f, pd = 0.f;
            #pragma unroll
            for (int nt = 0; nt < 4; ++nt) {
                #pragma unroll
                for (int ci = 0; ci < 2; ++ci) {
                    int col = wn * 32 + nt * 8 + 2 * tig + ci;
                    float a = acc[mt][nt][rh * 2 + ci];
                    ps += a * att_ss[col];
                    pd += a * att_ds[col];
                }
            }
            #pragma unroll
            for (int off = 1; off <= 2; off <<= 1) {
                ps += __shfl_xor_sync(0xffffffffu, ps, off);
                pd += __shfl_xor_sync(0xffffffffu, pd, off);
            }
            if (tig == 0 && n < NN) {
                asrc[n * 4 + wn] = ps;
                adst[n * 4 + wn] = pd;
            }
        }
    }

    // ---- stage accs to smem, then interleaved H store ----
    #pragma unroll
    for (int mt = 0; mt < 2; ++mt) {
        int rbase = wm * 32 + mt * 16 + g;
        #pragma unroll
        for (int nt = 0; nt < 4; ++nt) {
            int col = wn * 32 + nt * 8 + 2 * tig;
            stage[rbase * SP + col] = acc[mt][nt][0];
            stage[rbase * SP + col + 1] = acc[mt][nt][1];
            stage[(rbase + 8) * SP + col] = acc[mt][nt][2];
            stage[(rbase + 8) * SP + col + 1] = acc[mt][nt][3];
        }
    }
    __syncthreads();
    #pragma unroll 2
    for (int idx = t; idx < 128 * 32; idx += 512) {
        int r = idx >> 5, fc = idx & 31;
        int n = n0 + r;
        if (n < NN) {
            const float* sr = stage + r * SP;
            ((float4*)H)[(size_t)n * 32 + fc] =
                make_float4(sr[fc], sr[32 + fc], sr[64 + fc], sr[96 + fc]);
        }
    }
}

// ---------------- layer-4 GEMM via mma.sync tf32 (3xTF32): 256 rows x 32 cols ----------------
#define WP32 40   // B pitch (floats)
#define SP32 36   // stage pitch (floats)

__global__ __launch_bounds__(256, 2)
void gemm32_tc_kernel(const float* __restrict__ X, const float* __restrict__ W,
                      const float* __restrict__ att_s, const float* __restrict__ att_d,
                      float* __restrict__ H, float* __restrict__ asrc,
                      float* __restrict__ adst) {
    extern __shared__ char sh[];
    float* att_ss = (float*)sh;                        // 32 f
    float* att_ds = (float*)(sh + 512);                // 32 f
    uint32_t* xs_hi = (uint32_t*)(sh + 1024);          // [256][XP2]
    uint32_t* xs_lo = xs_hi + 256 * XP2;
    uint32_t* ws_hi = xs_lo + 256 * XP2;               // [32][WP32]
    uint32_t* ws_lo = ws_hi + 32 * WP32;
    float* stage = (float*)(sh + 1024);                // reused after mma

    int t = threadIdx.x;
    int lane = t & 31, wid = t >> 5;
    int g = lane >> 2, tig = lane & 3;
    int wm = wid;
    int n0 = blockIdx.x * 256;

    if (t < 32) { att_ss[t] = att_s[t]; att_ds[t] = att_d[t]; }

    float acc[2][4][4];
    #pragma unroll
    for (int mt = 0; mt < 2; ++mt)
        #pragma unroll
        for (int nt = 0; nt < 4; ++nt)
            #pragma unroll
            for (int i = 0; i < 4; ++i) acc[mt][nt][i] = 0.f;

    for (int kc = 0; kc < 4; ++kc) {
        #pragma unroll 4
        for (int idx = t; idx < 256 * 8; idx += 256) {
            int r = idx >> 3, c4 = idx & 7;
            int n = n0 + r;
            float4 v = make_float4(0.f, 0.f, 0.f, 0.f);
            if (n < NN) v = ((const float4*)X)[(size_t)n * 32 + kc * 8 + c4];
            float e[4] = {v.x, v.y, v.z, v.w};
            #pragma unroll
            for (int j = 0; j < 4; ++j) {
                uint32_t hu = f2tf(e[j]);
                float lo = e[j] - __uint_as_float(hu);
                xs_hi[r * XP2 + c4 * 4 + j] = hu;
                xs_lo[r * XP2 + c4 * 4 + j] = f2tf(lo);
            }
        }
        if (t < 256) {
            int kr = t >> 3, c4 = t & 7;
            if (kr < 32) {
                float4 v = ((const float4*)W)[(size_t)(kc * 32 + kr) * 8 + c4];
                float e[4] = {v.x, v.y, v.z, v.w};
                #pragma unroll
                for (int j = 0; j < 4; ++j) {
                    uint32_t hu = f2tf(e[j]);
                    float lo = e[j] - __uint_as_float(hu);
                    ws_hi[kr * WP32 + c4 * 4 + j] = hu;
                    ws_lo[kr * WP32 + c4 * 4 + j] = f2tf(lo);
                }
            }
        }
        __syncthreads();

        const uint32_t* xa_h = xs_hi + (wm * 32 + g) * XP2 + tig;
        const uint32_t* xa_l = xs_lo + (wm * 32 + g) * XP2 + tig;
        const uint32_t* wb_h = ws_hi + tig * WP32 + g;
        const uint32_t* wb_l = ws_lo + tig * WP32 + g;

        #pragma unroll
        for (int ks = 0; ks < 4; ++ks) {
            uint32_t ah[2][4], al[2][4];
            #pragma unroll
            for (int mt = 0; mt < 2; ++mt) {
                int base = mt * 16 * XP2 + ks * 8;
                ah[mt][0] = xa_h[base];
                ah[mt][1] = xa_h[base + 8 * XP2];
                ah[mt][2] = xa_h[base + 4];
                ah[mt][3] = xa_h[base + 8 * XP2 + 4];
                al[mt][0] = xa_l[base];
                al[mt][1] = xa_l[base + 8 * XP2];
                al[mt][2] = xa_l[base + 4];
                al[mt][3] = xa_l[base + 8 * XP2 + 4];
            }
            #pragma unroll
            for (int nt = 0; nt < 4; ++nt) {
                int boff = ks * 8 * WP32 + nt * 8;
                uint32_t bh0 = wb_h[boff], bh1 = wb_h[boff + 4 * WP32];
                uint32_t bl0 = wb_l[boff], bl1 = wb_l[boff + 4 * WP32];
                #pragma unroll
                for (int mt = 0; mt < 2; ++mt) {
                    mma_tf32(acc[mt][nt], ah[mt], bh0, bh1);
                    mma_tf32(acc[mt][nt], al[mt], bh0, bh1);
                    mma_tf32(acc[mt][nt], ah[mt], bl0, bl1);
                }
            }
        }
        __syncthreads();
    }

    #pragma unroll
    for (int mt = 0; mt < 2; ++mt) {
        #pragma unroll
        for (int rh = 0; rh < 2; ++rh) {
            int n = n0 + wm * 32 + mt * 16 + g + rh * 8;
            float ps = 0.f, pd = 0.f;
            #pragma unroll
            for (int nt = 0; nt < 4; ++nt) {
                #pragma unroll
                for (int ci = 0; ci < 2; ++ci) {
                    int col = nt * 8 + 2 * tig + ci;
                    float a = acc[mt][nt][rh * 2 + ci];
                    ps += a * att_ss[col];
                    pd += a * att_ds[col];
                }
            }
            #pragma unroll
            for (int off = 1; off <= 2; off <<= 1) {
                ps += __shfl_xor_sync(0xffffffffu, ps, off);
                pd += __shfl_xor_sync(0xffffffffu, pd, off);
            }
            if (tig == 0 && n < NN) {
                asrc[n] = ps;
                adst[n] = pd;
            }
        }
    }

    #pragma unroll
    for (int mt = 0; mt < 2; ++mt) {
        int rbase = wm * 32 + mt * 16 + g;
        #pragma unroll
        for (int nt = 0; nt < 4; ++nt) {
            int col = nt * 8 + 2 * tig;
            stage[rbase * SP32 + col] = acc[mt][nt][0];
            stage[rbase * SP32 + col + 1] = acc[mt][nt][1];
            stage[(rbase + 8) * SP32 + col] = acc[mt][nt][2];
            stage[(rbase + 8) * SP32 + col + 1] = acc[mt][nt][3];
        }
    }
    __syncthreads();
    #pragma unroll 4
    for (int idx = t; idx < 256 * 8; idx += 256) {
        int r = idx >> 3, fc = idx & 7;
        int n = n0 + r;
        if (n < NN)
            ((float4*)H)[(size_t)n * 8 + fc] = *(const float4*)(stage + r * SP32 + fc * 4);
    }
}

// ---------------- per-node ONLINE softmax + aggregation (MLP=4 gather) ----------------
__device__ __forceinline__ float lrelu(float v) { return fmaxf(v, 0.2f * v); }

template <int HEADS, int ACT>   // ACT: 0 = ELU, 1 = sigmoid
__launch_bounds__(256)
__global__ void agg_kernel(const float* __restrict__ feat,
                           const float* __restrict__ asrc, const float* __restrict__ adst,
                           const float* __restrict__ bias, float* __restrict__ out) {
    __shared__ float4 s_w4[8][32];
    __shared__ int s_src[8][32];
    int wid = threadIdx.x >> 5;
    int lane = threadIdx.x & 31;
    int n = blockIdx.x * 8 + wid;
    if (n >= NN) return;
    int beg = g_ptr[n], end = g_ptr[n + 1];
    const float4* feat4 = (const float4*)feat;

    if (HEADS == 4) {
        float4 ad = ((const float4*)adst)[n];
        float m0 = -1e30f, m1 = -1e30f, m2 = -1e30f, m3 = -1e30f;
        float a0 = 0.f, a1 = 0.f, a2 = 0.f, a3 = 0.f;
        float s0 = 0.f, s1 = 0.f, s2 = 0.f, s3 = 0.f;
        for (int base = beg; base < end; base += 32) {
            int cnt = min(32, end - base);
            float l0 = -1e30f, l1 = -1e30f, l2 = -1e30f, l3 = -1e30f;
            int src = 0;
            if (lane < cnt) {
                src = g_csr[base + lane];
                float4 a = ((const float4*)asrc)[src];
                l0 = lrelu(a.x + ad.x);
                l1 = lrelu(a.y + ad.y);
                l2 = lrelu(a.z + ad.z);
                l3 = lrelu(a.w + ad.w);
            }
            float c0 = l0, c1 = l1, c2 = l2, c3 = l3;
            #pragma unroll
            for (int off = 16; off >= 1; off >>= 1) {
                c0 = fmaxf(c0, __shfl_xor_sync(0xffffffffu, c0, off));
                c1 = fmaxf(c1, __shfl_xor_sync(0xffffffffu, c1, off));
                c2 = fmaxf(c2, __shfl_xor_sync(0xffffffffu, c2, off));
                c3 = fmaxf(c3, __shfl_xor_sync(0xffffffffu, c3, off));
            }
            float nm0 = fmaxf(m0, c0), nm1 = fmaxf(m1, c1);
            float nm2 = fmaxf(m2, c2), nm3 = fmaxf(m3, c3);
            float f0 = __expf(m0 - nm0), f1 = __expf(m1 - nm1);
            float f2 = __expf(m2 - nm2), f3 = __expf(m3 - nm3);
            a0 *= f0; a1 *= f1; a2 *= f2; a3 *= f3;
            s0 *= f0; s1 *= f1; s2 *= f2; s3 *= f3;
            m0 = nm0; m1 = nm1; m2 = nm2; m3 = nm3;
            if (lane < cnt) {
                float4 wv;
                wv.x = __expf(l0 - m0);
                wv.y = __expf(l1 - m1);
                wv.z = __expf(l2 - m2);
                wv.w = __expf(l3 - m3);
                s_w4[wid][lane] = wv;
                s_src[wid][lane] = src;
            }
            __syncwarp();
            int i = 0;
            for (; i + 4 <= cnt; i += 4) {   // MLP=4: 4 independent gathers in flight
                float4 w0 = s_w4[wid][i],     w1 = s_w4[wid][i + 1];
                float4 w2 = s_w4[wid][i + 2], w3 = s_w4[wid][i + 3];
                int p0 = s_src[wid][i],     p1 = s_src[wid][i + 1];
                int p2 = s_src[wid][i + 2], p3 = s_src[wid][i + 3];
                float4 v0 = feat4[(size_t)p0 * 32 + lane];
                float4 v1 = feat4[(size_t)p1 * 32 + lane];
                float4 v2 = feat4[(size_t)p2 * 32 + lane];
                float4 v3 = feat4[(size_t)p3 * 32 + lane];
                a0 += w0.x * v0.x; a1 += w0.y * v0.y; a2 += w0.z * v0.z; a3 += w0.w * v0.w;
                a0 += w1.x * v1.x; a1 += w1.y * v1.y; a2 += w1.z * v1.z; a3 += w1.w * v1.w;
                a0 += w2.x * v2.x; a1 += w2.y * v2.y; a2 += w2.z * v2.z; a3 += w2.w * v2.w;
                a0 += w3.x * v3.x; a1 += w3.y * v3.y; a2 += w3.z * v3.z; a3 += w3.w * v3.w;
                s0 += w0.x + w1.x + w2.x + w3.x;
                s1 += w0.y + w1.y + w2.y + w3.y;
                s2 += w0.z + w1.z + w2.z + w3.z;
                s3 += w0.w + w1.w + w2.w + w3.w;
            }
            for (; i < cnt; ++i) {
                float4 wv = s_w4[wid][i];
                int si = s_src[wid][i];
                float4 v = feat4[(size_t)si * 32 + lane];
                a0 += wv.x * v.x; a1 += wv.y * v.y; a2 += wv.z * v.z; a3 += wv.w * v.w;
                s0 += wv.x; s1 += wv.y; s2 += wv.z; s3 += wv.w;
            }
            __syncwarp();
        }
        float o0 = a0 / s0 + bias[lane];
        float o1 = a1 / s1 + bias[32 + lane];
        float o2 = a2 / s2 + bias[64 + lane];
        float o3 = a3 / s3 + bias[96 + lane];
        o0 = (o0 > 0.f) ? o0 : (__expf(o0) - 1.f);
        o1 = (o1 > 0.f) ? o1 : (__expf(o1) - 1.f);
        o2 = (o2 > 0.f) ? o2 : (__expf(o2) - 1.f);
        o3 = (o3 > 0.f) ? o3 : (__expf(o3) - 1.f);
        size_t b = (size_t)n * 128;
        out[b + lane] = o0;
        out[b + 32 + lane] = o1;
        out[b + 64 + lane] = o2;
        out[b + 96 + lane] = o3;
    } else {
        float* s_wf = (float*)&s_w4[wid][0];
        float ad = adst[n];
        float m = -1e30f, acc = 0.f, ssum = 0.f;
        for (int base = beg; base < end; base += 32) {
            int cnt = min(32, end - base);
            float l = -1e30f;
            int src = 0;
            if (lane < cnt) {
                src = g_csr[base + lane];
                l = lrelu(asrc[src] + ad);
            }
            float c = l;
            #pragma unroll
            for (int off = 16; off >= 1; off >>= 1)
                c = fmaxf(c, __shfl_xor_sync(0xffffffffu, c, off));
            float nm = fmaxf(m, c);
            float f = __expf(m - nm);
            acc *= f; ssum *= f;
            m = nm;
            if (lane < cnt) {
                s_wf[lane] = __expf(l - m);
                s_src[wid][lane] = src;
            }
            __syncwarp();
            int i = 0;
            for (; i + 4 <= cnt; i += 4) {
                float w0 = s_wf[i], w1 = s_wf[i + 1], w2 = s_wf[i + 2], w3 = s_wf[i + 3];
                int p0 = s_src[wid][i],     p1 = s_src[wid][i + 1];
                int p2 = s_src[wid][i + 2], p3 = s_src[wid][i + 3];
                float v0 = feat[(size_t)p0 * 32 + lane];
                float v1 = feat[(size_t)p1 * 32 + lane];
                float v2 = feat[(size_t)p2 * 32 + lane];
                float v3 = feat[(size_t)p3 * 32 + lane];
                acc += w0 * v0 + w1 * v1 + w2 * v2 + w3 * v3;
                ssum += w0 + w1 + w2 + w3;
            }
            for (; i < cnt; ++i) {
                float wi = s_wf[i];
                int si = s_src[wid][i];
                acc += wi * feat[(size_t)si * 32 + lane];
                ssum += wi;
            }
            __syncwarp();
        }
        float o = acc / ssum + bias[lane];
        o = 1.f / (1.f + __expf(-o));
        out[(size_t)n * 32 + lane] = o;
    }
}

// ---------------- host launcher (single stream, capture-safe) ----------------
extern "C" void kernel_launch(void* const* d_in, const int* in_sizes, int n_in,
                              void* d_out, int out_size) {
    const float* x = (const float*)d_in[0];
    const void* ei = d_in[1];
    const float* W[4]  = {(const float*)d_in[2], (const float*)d_in[6],
                          (const float*)d_in[10], (const float*)d_in[14]};
    const float* As[4] = {(const float*)d_in[3], (const float*)d_in[7],
                          (const float*)d_in[11], (const float*)d_in[15]};
    const float* Ad[4] = {(const float*)d_in[4], (const float*)d_in[8],
                          (const float*)d_in[12], (const float*)d_in[16]};
    const float* B[4]  = {(const float*)d_in[5], (const float*)d_in[9],
                          (const float*)d_in[13], (const float*)d_in[17]};
    float* out = (float*)d_out;

    float *p_h0, *p_h1, *p_asrc, *p_adst;
    cudaGetSymbolAddress((void**)&p_h0, g_h0);
    cudaGetSymbolAddress((void**)&p_h1, g_h1);
    cudaGetSymbolAddress((void**)&p_asrc, g_asrc);
    cudaGetSymbolAddress((void**)&p_adst, g_adst);

    constexpr int SMEM_TC = 1024 + (2 * 128 * XP2 + 2 * 32 * WP) * 4;    // 72704 B
    constexpr int SMEM_32 = 1024 + (2 * 256 * XP2 + 2 * 32 * WP32) * 4;  // 84992 B
    cudaFuncSetAttribute(gemm_tc_kernel,
                         cudaFuncAttributeMaxDynamicSharedMemorySize, SMEM_TC);
    cudaFuncSetAttribute(gemm32_tc_kernel,
                         cudaFuncAttributeMaxDynamicSharedMemorySize, SMEM_32);

    const int GTC = (NN + 127) / 128;   // 391
    const int G32 = (NN + 255) / 256;   // 196
    const int AB = (NN + 7) / 8;        // 6250

    // CSR build (fused launches); layer-1 GEMM at index 3 for ncu capture.
    detect_init_kernel<<<(NN + 255) / 256, 256>>>((const int*)ei);         // 0
    hist_kernel<<<(EE + 255) / 256, 256>>>(ei);                            // 1
    scan_local_kernel<<<NBS, 1024>>>();                                    // 2
    gemm_tc_kernel<<<GTC, 512, SMEM_TC>>>(x, W[0], As[0], Ad[0],           // 3 (profiled)
                                          p_h1, p_asrc, p_adst);
    scan_add_kernel<<<NBS, 1024>>>();                                      // 4
    scatter_kernel<<<(EE + 255) / 256, 256>>>(ei);                         // 5

    // layer 1 aggregation
    agg_kernel<4, 0><<<AB, 256>>>(p_h1, p_asrc, p_adst, B[0], p_h0);
    // layer 2
    gemm_tc_kernel<<<GTC, 512, SMEM_TC>>>(p_h0, W[1], As[1], Ad[1], p_h1, p_asrc, p_adst);
    agg_kernel<4, 0><<<AB, 256>>>(p_h1, p_asrc, p_adst, B[1], p_h0);
    // layer 3
    gemm_tc_kernel<<<GTC, 512, SMEM_TC>>>(p_h0, W[2], As[2], Ad[2], p_h1, p_asrc, p_adst);
    agg_kernel<4, 0><<<AB, 256>>>(p_h1, p_asrc, p_adst, B[2], p_h0);
    // layer 4 (heads=1, 32 labels) -> sigmoid -> d_out
    gemm32_tc_kernel<<<G32, 256, SMEM_32>>>(p_h0, W[3], As[3], Ad[3], p_h1, p_asrc, p_adst);
    agg_kernel<1, 1><<<AB, 256>>>(p_h1, p_asrc, p_adst, B[3], out);
}